// round 4
// baseline (speedup 1.0000x reference)
#include <cuda_runtime.h>
#include <cuda_bf16.h>
#include <mma.h>
#include <math.h>
#include <stdint.h>

using namespace nvcuda;

// Problem constants
#define NTOK   16384      // B*S
#define DMODEL 1024
#define NHEAD  16
#define HD     64
#define NP     32
#define NR     8
#define NPR    256

// Scratch (allocation-free rule)
__device__ float g_heads[(size_t)NTOK * DMODEL];     // tf32-rounded heads
__device__ float g_W32[(size_t)DMODEL * DMODEL];     // tf32-rounded W_out [K,N]
__device__ float g_biasrep[16 * DMODEL];             // bias replicated 16 rows

// ---------------------------------------------------------------------------
__device__ __forceinline__ uint32_t smem_u32(const void* p) {
    uint32_t a;
    asm("{ .reg .u64 t; cvta.to.shared.u64 t, %1; cvt.u32.u64 %0, t; }"
        : "=r"(a) : "l"(p));
    return a;
}
#define CP_ASYNC16(dst, src) \
    asm volatile("cp.async.cg.shared.global [%0], [%1], 16;" :: "r"(dst), "l"(src))
#define CP_COMMIT() asm volatile("cp.async.commit_group;" ::: "memory")
#define CP_WAIT1()  asm volatile("cp.async.wait_group 1;" ::: "memory")

// ---------------------------------------------------------------------------
// Warp reduction helpers
// ---------------------------------------------------------------------------
__device__ __forceinline__ float warp_max(float v) {
#pragma unroll
    for (int o = 16; o > 0; o >>= 1) v = fmaxf(v, __shfl_xor_sync(0xffffffffu, v, o));
    return v;
}
__device__ __forceinline__ float warp_sum(float v) {
#pragma unroll
    for (int o = 16; o > 0; o >>= 1) v += __shfl_xor_sync(0xffffffffu, v, o);
    return v;
}
__device__ __forceinline__ float g8_max(float v) {
#pragma unroll
    for (int o = 4; o > 0; o >>= 1) v = fmaxf(v, __shfl_xor_sync(0xffffffffu, v, o));
    return v;
}
__device__ __forceinline__ float g8_sum(float v) {
#pragma unroll
    for (int o = 4; o > 0; o >>= 1) v += __shfl_xor_sync(0xffffffffu, v, o);
    return v;
}

// ---------------------------------------------------------------------------
// Attention kernel: one block = (head, 512-token chunk), 16 warps.
// ---------------------------------------------------------------------------
#define ATTN_THREADS 512
#define ATTN_WARPS   16
#define TOK_PER_BLK  512
#define ATTN_SMEM_FLOATS (2048 + 16384 + 16384 + ATTN_WARPS * 64)

__global__ __launch_bounds__(ATTN_THREADS) void attn_kernel(
    const float* __restrict__ x,
    const float* __restrict__ Kst,
    const float* __restrict__ Vst,
    const float* __restrict__ Wrt)
{
    extern __shared__ float sm[];
    float* Wr_s = sm;                 // [64][32]
    float* Ks   = sm + 2048;          // [64][256]
    float* Vs   = Ks + 16384;         // [256][64]
    float* xs   = Vs + 16384;         // [16][64]

    const int h    = blockIdx.x;
    const int tid  = threadIdx.x;
    const int wid  = tid >> 5;
    const int lane = tid & 31;
    const unsigned FULL = 0xffffffffu;

    for (int i = tid; i < HD * NP; i += ATTN_THREADS)
        Wr_s[i] = Wrt[h * HD * NP + i];
    const float* Kh = Kst + (size_t)h * NPR * HD;
    for (int i = tid; i < NPR * HD; i += ATTN_THREADS) {
        int d = i & 63, pr = i >> 6;
        Ks[d * NPR + pr] = Kh[i];
    }
    const float* Vh = Vst + (size_t)h * NPR * HD;
    for (int i = tid; i < NPR * HD; i += ATTN_THREADS)
        Vs[i] = Vh[i];
    __syncthreads();

    float* xw = xs + wid * 64;
    const int e8 = lane >> 3;
    const int r8 = lane & 7;

    for (int it = 0; it < TOK_PER_BLK / ATTN_WARPS; ++it) {
        const int tk = blockIdx.y * TOK_PER_BLK + it * ATTN_WARPS + wid;
        const float* xp = x + (size_t)tk * DMODEL + h * HD;

        float2 xv = ((const float2*)xp)[lane];
        xw[2 * lane]     = xv.x;
        xw[2 * lane + 1] = xv.y;
        __syncwarp();

        // ---- router logits (4 accumulators) ----
        float l0 = 0.f, l1 = 0.f, l2 = 0.f, l3 = 0.f;
#pragma unroll
        for (int d = 0; d < HD; d += 4) {
            l0 = fmaf(xw[d],     Wr_s[d * NP + lane],       l0);
            l1 = fmaf(xw[d + 1], Wr_s[(d + 1) * NP + lane], l1);
            l2 = fmaf(xw[d + 2], Wr_s[(d + 2) * NP + lane], l2);
            l3 = fmaf(xw[d + 3], Wr_s[(d + 3) * NP + lane], l3);
        }
        float lg = (l0 + l1) + (l2 + l3);

        // ---- top-4 threshold ----
        float m0  = warp_max(lg);
        float cur = lg, mm = m0;
#pragma unroll
        for (int i = 0; i < 3; ++i) {
            cur = (cur == mm) ? -INFINITY : cur;
            mm  = warp_max(cur);
        }
        const bool sel = (lg >= mm);
        float ev   = sel ? __expf(lg - m0) : 0.f;
        float gate = ev / warp_sum(ev);

        unsigned bal = __ballot_sync(FULL, sel);
        int pa0, pa1, pa2, pa3;
        {
            unsigned b = bal;
            pa0 = __ffs(b) - 1; b &= b - 1;
            pa1 = __ffs(b) - 1; b &= b - 1;
            pa2 = __ffs(b) - 1; b &= b - 1;
            pa3 = __ffs(b) - 1;
            if (pa0 < 0) pa0 = 0;
            if (pa1 < 0) pa1 = pa0;
            if (pa2 < 0) pa2 = pa1;
            if (pa3 < 0) pa3 = pa2;
        }
        const float ga0 = __shfl_sync(FULL, gate, pa0);
        const float ga1 = __shfl_sync(FULL, gate, pa1);
        const float ga2 = __shfl_sync(FULL, gate, pa2);
        const float ga3 = __shfl_sync(FULL, gate, pa3);

        const int   p_my = (e8 == 0) ? pa0 : (e8 == 1) ? pa1 : (e8 == 2) ? pa2 : pa3;
        const float g_my = (e8 == 0) ? ga0 : (e8 == 1) ? ga1 : (e8 == 2) ? ga2 : ga3;

        // ---- scores (4 accumulators) ----
        const float* kc = Ks + p_my * NR + r8;
        float s0 = 0.f, s1 = 0.f, s2 = 0.f, s3 = 0.f;
#pragma unroll
        for (int d = 0; d < HD; d += 4) {
            s0 = fmaf(xw[d],     kc[d * NPR],       s0);
            s1 = fmaf(xw[d + 1], kc[(d + 1) * NPR], s1);
            s2 = fmaf(xw[d + 2], kc[(d + 2) * NPR], s2);
            s3 = fmaf(xw[d + 3], kc[(d + 3) * NPR], s3);
        }
        float sc = ((s0 + s1) + (s2 + s3)) * 0.125f;

        const float sm8 = g8_max(sc);
        const float ex  = __expf(sc - sm8);
        const float wv  = (ex / g8_sum(ex)) * g_my;

        // ---- combine: lane owns dims (2*lane, 2*lane+1); float2 LDS ----
        float a0x = 0.f, a0y = 0.f, a1x = 0.f, a1y = 0.f;
#pragma unroll
        for (int j = 0; j < 32; j += 2) {
            const float wj0 = __shfl_sync(FULL, wv, j);
            const float wj1 = __shfl_sync(FULL, wv, j + 1);
            const int pj0 = (j < 8) ? pa0 : (j < 16) ? pa1 : (j < 24) ? pa2 : pa3;
            const int jb  = j + 1;
            const int pj1 = (jb < 8) ? pa0 : (jb < 16) ? pa1 : (jb < 24) ? pa2 : pa3;
            const float2 v0 = ((const float2*)(Vs + (pj0 * NR + (j & 7)) * HD))[lane];
            const float2 v1 = ((const float2*)(Vs + (pj1 * NR + (jb & 7)) * HD))[lane];
            a0x = fmaf(wj0, v0.x, a0x);
            a0y = fmaf(wj0, v0.y, a0y);
            a1x = fmaf(wj1, v1.x, a1x);
            a1y = fmaf(wj1, v1.y, a1y);
        }

        // store tf32-rounded so GEMM can consume raw bits
        float2 o2;
        o2.x = wmma::__float_to_tf32(a0x + a1x);
        o2.y = wmma::__float_to_tf32(a0y + a1y);
        *(float2*)(g_heads + (size_t)tk * DMODEL + h * HD + 2 * lane) = o2;
        __syncwarp();
    }
}

// ---------------------------------------------------------------------------
// Convert W_out -> tf32 and replicate bias into 16 rows
// ---------------------------------------------------------------------------
__global__ __launch_bounds__(256) void convert_kernel(
    const float* __restrict__ W, const float* __restrict__ bias)
{
    const int idx = blockIdx.x * 256 + threadIdx.x;           // float4 index
    const int n4 = DMODEL * DMODEL / 4;                       // 262144
    if (idx < n4) {
        float4 v = ((const float4*)W)[idx];
        v.x = wmma::__float_to_tf32(v.x);
        v.y = wmma::__float_to_tf32(v.y);
        v.z = wmma::__float_to_tf32(v.z);
        v.w = wmma::__float_to_tf32(v.w);
        ((float4*)g_W32)[idx] = v;
    }
    if (idx < 16 * DMODEL / 4) {
        float4 b = ((const float4*)bias)[idx & (DMODEL / 4 - 1)];
        ((float4*)g_biasrep)[idx] = b;
    }
}

// ---------------------------------------------------------------------------
// GEMM: C[16384,1024] = g_heads(tf32) @ g_W32(tf32) + bias
// Block 128x128, K-tile 32, 8 warps (4Mx2N), warp tile 32x64,
// 3-stage cp.async pipeline. WMMA tf32 m16n16k8.
// NOTE: all scratch accessed via device-code symbol references ONLY
// (host code must never touch __device__ symbols — R3 bug).
// ---------------------------------------------------------------------------
#define GM 16384
#define GN 1024
#define GK 1024
#define BM 128
#define BN 128
#define BK 32
#define NKT (GK / BK)        // 32
#define LDA 36               // padded A smem row (floats)
#define LDB 132              // padded B smem row (floats)
#define A_STG (BM * LDA)     // 4608 floats per stage
#define B_STG (BK * LDB)     // 4224 floats per stage
#define GEMM_SMEM ((3 * (A_STG + B_STG)) * 4)   // 105984 bytes

__global__ __launch_bounds__(256, 2) void gemm_kernel(float* __restrict__ C)
{
    extern __shared__ __align__(16) float smg[];
    const int tid = threadIdx.x;
    const int wid = tid >> 5;
    const int wm  = wid & 3;            // 0..3 (M)
    const int wn  = wid >> 2;           // 0..1 (N)
    const int bm  = blockIdx.y * BM;
    const int bn  = blockIdx.x * BN;

    const float* Ag  = g_heads + (size_t)bm * GK;
    const float* Bgp = g_W32 + bn;

    const uint32_t smem_b = smem_u32(smg);

    // accumulators init from replicated bias (global load)
    wmma::fragment<wmma::accumulator, 16, 16, 8, float> cf[2][4];
#pragma unroll
    for (int i = 0; i < 2; ++i)
#pragma unroll
        for (int j = 0; j < 4; ++j)
            wmma::load_matrix_sync(cf[i][j], g_biasrep + bn + wn * 64 + j * 16,
                                   GN, wmma::mem_row_major);

    // per-thread cp.async source/dest decomposition
    const int arow = tid >> 3;          // 0..31 (+32 per iter), A: 128 rows x 8 f4
    const int acol = (tid & 7) << 2;    // float col 0..28
    const int brow = tid >> 5;          // 0..7 (+8 per iter),  B: 32 rows x 32 f4
    const int bcol = (tid & 31) << 2;

    auto load_stage = [&](int kt, int s) {
        const int kof = kt * BK;
        uint32_t adst = smem_b + (s * A_STG) * 4;
        uint32_t bdst = smem_b + (3 * A_STG + s * B_STG) * 4;
#pragma unroll
        for (int i = 0; i < 4; ++i) {
            const int r = arow + i * 32;
            CP_ASYNC16(adst + (r * LDA + acol) * 4,
                       Ag + (size_t)r * GK + kof + acol);
        }
#pragma unroll
        for (int i = 0; i < 4; ++i) {
            const int r = brow + i * 8;
            CP_ASYNC16(bdst + (r * LDB + bcol) * 4,
                       Bgp + (size_t)(kof + r) * GN + bcol);
        }
    };

    load_stage(0, 0); CP_COMMIT();
    load_stage(1, 1); CP_COMMIT();

    for (int c = 0; c < NKT; ++c) {
        const int s = c % 3;
        CP_WAIT1();
        __syncthreads();
        if (c + 2 < NKT) load_stage(c + 2, (c + 2) % 3);
        CP_COMMIT();

        const float* As = smg + s * A_STG;
        const float* Bs = smg + 3 * A_STG + s * B_STG;
#pragma unroll
        for (int k0 = 0; k0 < BK; k0 += 8) {
            wmma::fragment<wmma::matrix_a, 16, 16, 8, wmma::precision::tf32,
                           wmma::row_major> af[2];
            wmma::fragment<wmma::matrix_b, 16, 16, 8, wmma::precision::tf32,
                           wmma::row_major> bf[4];
#pragma unroll
            for (int i = 0; i < 2; ++i)
                wmma::load_matrix_sync(af[i], As + (wm * 32 + i * 16) * LDA + k0, LDA);
#pragma unroll
            for (int j = 0; j < 4; ++j)
                wmma::load_matrix_sync(bf[j], Bs + k0 * LDB + wn * 64 + j * 16, LDB);
#pragma unroll
            for (int i = 0; i < 2; ++i)
#pragma unroll
                for (int j = 0; j < 4; ++j)
                    wmma::mma_sync(cf[i][j], af[i], bf[j], cf[i][j]);
        }
        __syncthreads();
    }

#pragma unroll
    for (int i = 0; i < 2; ++i)
#pragma unroll
        for (int j = 0; j < 4; ++j)
            wmma::store_matrix_sync(
                C + (size_t)(bm + wm * 32 + i * 16) * GN + bn + wn * 64 + j * 16,
                cf[i][j], GN, wmma::mem_row_major);
}

// ---------------------------------------------------------------------------
extern "C" void kernel_launch(void* const* d_in, const int* in_sizes, int n_in,
                              void* d_out, int out_size)
{
    const float* x    = (const float*)d_in[0];
    const float* Kst  = (const float*)d_in[1];
    const float* Vst  = (const float*)d_in[2];
    const float* Wrt  = (const float*)d_in[3];
    const float* Wout = (const float*)d_in[4];
    const float* bout = (const float*)d_in[5];
    float* out = (float*)d_out;

    const int attn_smem = ATTN_SMEM_FLOATS * (int)sizeof(float);
    cudaFuncSetAttribute(attn_kernel,
                         cudaFuncAttributeMaxDynamicSharedMemorySize, attn_smem);
    cudaFuncSetAttribute(gemm_kernel,
                         cudaFuncAttributeMaxDynamicSharedMemorySize, GEMM_SMEM);

    convert_kernel<<<DMODEL * DMODEL / 4 / 256, 256>>>(Wout, bout);
    attn_kernel<<<dim3(NHEAD, NTOK / TOK_PER_BLK), ATTN_THREADS, attn_smem>>>(
        x, Kst, Vst, Wrt);
    gemm_kernel<<<dim3(GN / BN, GM / BM), 256, GEMM_SMEM>>>(out);
}

// round 5
// speedup vs baseline: 1.4774x; 1.4774x over previous
#include <cuda_runtime.h>
#include <cuda_bf16.h>
#include <mma.h>
#include <math.h>
#include <stdint.h>

using namespace nvcuda;

// Problem constants
#define NTOK   16384      // B*S
#define DMODEL 1024
#define NHEAD  16
#define HD     64
#define NP     32
#define NR     8
#define NPR    256

// Scratch (allocation-free rule)
__device__ float g_heads[(size_t)NTOK * DMODEL];     // tf32-rounded heads
__device__ float g_W32[(size_t)DMODEL * DMODEL];     // tf32-rounded W_out [K,N]
__device__ float g_biasrep[16 * DMODEL];             // bias replicated 16 rows

// ---------------------------------------------------------------------------
__device__ __forceinline__ uint32_t smem_u32(const void* p) {
    uint32_t a;
    asm("{ .reg .u64 t; cvta.to.shared.u64 t, %1; cvt.u32.u64 %0, t; }"
        : "=r"(a) : "l"(p));
    return a;
}
#define CP_ASYNC16(dst, src) \
    asm volatile("cp.async.cg.shared.global [%0], [%1], 16;" :: "r"(dst), "l"(src))
#define CP_COMMIT() asm volatile("cp.async.commit_group;" ::: "memory")
#define CP_WAIT1()  asm volatile("cp.async.wait_group 1;" ::: "memory")

// ---------------------------------------------------------------------------
// Warp reduction helpers
// ---------------------------------------------------------------------------
__device__ __forceinline__ float warp_max(float v) {
#pragma unroll
    for (int o = 16; o > 0; o >>= 1) v = fmaxf(v, __shfl_xor_sync(0xffffffffu, v, o));
    return v;
}
__device__ __forceinline__ float warp_sum(float v) {
#pragma unroll
    for (int o = 16; o > 0; o >>= 1) v += __shfl_xor_sync(0xffffffffu, v, o);
    return v;
}
__device__ __forceinline__ float g8_max(float v) {
#pragma unroll
    for (int o = 4; o > 0; o >>= 1) v = fmaxf(v, __shfl_xor_sync(0xffffffffu, v, o));
    return v;
}
__device__ __forceinline__ float g8_sum(float v) {
#pragma unroll
    for (int o = 4; o > 0; o >>= 1) v += __shfl_xor_sync(0xffffffffu, v, o);
    return v;
}

// ---------------------------------------------------------------------------
// Attention kernel: one block = (head, 512-token chunk), 32 warps now
// (smem forces 1 CTA/SM; 1024 threads doubles warps/SMSP for latency hiding).
// ---------------------------------------------------------------------------
#define ATTN_THREADS 1024
#define ATTN_WARPS   32
#define TOK_PER_BLK  512
#define ATTN_SMEM_FLOATS (2048 + 16384 + 16384 + ATTN_WARPS * 64)

__global__ __launch_bounds__(ATTN_THREADS) void attn_kernel(
    const float* __restrict__ x,
    const float* __restrict__ Kst,
    const float* __restrict__ Vst,
    const float* __restrict__ Wrt)
{
    extern __shared__ float sm[];
    float* Wr_s = sm;                 // [64][32]
    float* Ks   = sm + 2048;          // [64][256]
    float* Vs   = Ks + 16384;         // [256][64]
    float* xs   = Vs + 16384;         // [32][64]

    const int h    = blockIdx.x;
    const int tid  = threadIdx.x;
    const int wid  = tid >> 5;
    const int lane = tid & 31;
    const unsigned FULL = 0xffffffffu;

    for (int i = tid; i < HD * NP; i += ATTN_THREADS)
        Wr_s[i] = Wrt[h * HD * NP + i];
    const float* Kh = Kst + (size_t)h * NPR * HD;
    for (int i = tid; i < NPR * HD; i += ATTN_THREADS) {
        int d = i & 63, pr = i >> 6;
        Ks[d * NPR + pr] = Kh[i];
    }
    const float* Vh = Vst + (size_t)h * NPR * HD;
    for (int i = tid; i < NPR * HD; i += ATTN_THREADS)
        Vs[i] = Vh[i];
    __syncthreads();

    float* xw = xs + wid * 64;
    const int e8 = lane >> 3;
    const int r8 = lane & 7;

    for (int it = 0; it < TOK_PER_BLK / ATTN_WARPS; ++it) {
        const int tk = blockIdx.y * TOK_PER_BLK + it * ATTN_WARPS + wid;
        const float* xp = x + (size_t)tk * DMODEL + h * HD;

        float2 xv = ((const float2*)xp)[lane];
        xw[2 * lane]     = xv.x;
        xw[2 * lane + 1] = xv.y;
        __syncwarp();

        // ---- router logits (4 accumulators) ----
        float l0 = 0.f, l1 = 0.f, l2 = 0.f, l3 = 0.f;
#pragma unroll
        for (int d = 0; d < HD; d += 4) {
            l0 = fmaf(xw[d],     Wr_s[d * NP + lane],       l0);
            l1 = fmaf(xw[d + 1], Wr_s[(d + 1) * NP + lane], l1);
            l2 = fmaf(xw[d + 2], Wr_s[(d + 2) * NP + lane], l2);
            l3 = fmaf(xw[d + 3], Wr_s[(d + 3) * NP + lane], l3);
        }
        float lg = (l0 + l1) + (l2 + l3);

        // ---- top-4 threshold ----
        float m0  = warp_max(lg);
        float cur = lg, mm = m0;
#pragma unroll
        for (int i = 0; i < 3; ++i) {
            cur = (cur == mm) ? -INFINITY : cur;
            mm  = warp_max(cur);
        }
        const bool sel = (lg >= mm);
        float ev   = sel ? __expf(lg - m0) : 0.f;
        float gate = ev / warp_sum(ev);

        unsigned bal = __ballot_sync(FULL, sel);
        int pa0, pa1, pa2, pa3;
        {
            unsigned b = bal;
            pa0 = __ffs(b) - 1; b &= b - 1;
            pa1 = __ffs(b) - 1; b &= b - 1;
            pa2 = __ffs(b) - 1; b &= b - 1;
            pa3 = __ffs(b) - 1;
            if (pa0 < 0) pa0 = 0;
            if (pa1 < 0) pa1 = pa0;
            if (pa2 < 0) pa2 = pa1;
            if (pa3 < 0) pa3 = pa2;
        }
        const float ga0 = __shfl_sync(FULL, gate, pa0);
        const float ga1 = __shfl_sync(FULL, gate, pa1);
        const float ga2 = __shfl_sync(FULL, gate, pa2);
        const float ga3 = __shfl_sync(FULL, gate, pa3);

        const int   p_my = (e8 == 0) ? pa0 : (e8 == 1) ? pa1 : (e8 == 2) ? pa2 : pa3;
        const float g_my = (e8 == 0) ? ga0 : (e8 == 1) ? ga1 : (e8 == 2) ? ga2 : ga3;

        // ---- scores (4 accumulators) ----
        const float* kc = Ks + p_my * NR + r8;
        float s0 = 0.f, s1 = 0.f, s2 = 0.f, s3 = 0.f;
#pragma unroll
        for (int d = 0; d < HD; d += 4) {
            s0 = fmaf(xw[d],     kc[d * NPR],       s0);
            s1 = fmaf(xw[d + 1], kc[(d + 1) * NPR], s1);
            s2 = fmaf(xw[d + 2], kc[(d + 2) * NPR], s2);
            s3 = fmaf(xw[d + 3], kc[(d + 3) * NPR], s3);
        }
        float sc = ((s0 + s1) + (s2 + s3)) * 0.125f;

        const float sm8 = g8_max(sc);
        const float ex  = __expf(sc - sm8);
        const float wv  = (ex / g8_sum(ex)) * g_my;

        // ---- combine: lane owns dims (2*lane, 2*lane+1); float2 LDS ----
        float a0x = 0.f, a0y = 0.f, a1x = 0.f, a1y = 0.f;
#pragma unroll
        for (int j = 0; j < 32; j += 2) {
            const float wj0 = __shfl_sync(FULL, wv, j);
            const float wj1 = __shfl_sync(FULL, wv, j + 1);
            const int pj0 = (j < 8) ? pa0 : (j < 16) ? pa1 : (j < 24) ? pa2 : pa3;
            const int jb  = j + 1;
            const int pj1 = (jb < 8) ? pa0 : (jb < 16) ? pa1 : (jb < 24) ? pa2 : pa3;
            const float2 v0 = ((const float2*)(Vs + (pj0 * NR + (j & 7)) * HD))[lane];
            const float2 v1 = ((const float2*)(Vs + (pj1 * NR + (jb & 7)) * HD))[lane];
            a0x = fmaf(wj0, v0.x, a0x);
            a0y = fmaf(wj0, v0.y, a0y);
            a1x = fmaf(wj1, v1.x, a1x);
            a1y = fmaf(wj1, v1.y, a1y);
        }

        // store tf32-rounded so GEMM can consume raw bits
        float2 o2;
        o2.x = wmma::__float_to_tf32(a0x + a1x);
        o2.y = wmma::__float_to_tf32(a0y + a1y);
        *(float2*)(g_heads + (size_t)tk * DMODEL + h * HD + 2 * lane) = o2;
        __syncwarp();
    }
}

// ---------------------------------------------------------------------------
// Convert W_out -> tf32 and replicate bias into 16 rows
// ---------------------------------------------------------------------------
__global__ __launch_bounds__(256) void convert_kernel(
    const float* __restrict__ W, const float* __restrict__ bias)
{
    const int idx = blockIdx.x * 256 + threadIdx.x;           // float4 index
    const int n4 = DMODEL * DMODEL / 4;                       // 262144
    if (idx < n4) {
        float4 v = ((const float4*)W)[idx];
        v.x = wmma::__float_to_tf32(v.x);
        v.y = wmma::__float_to_tf32(v.y);
        v.z = wmma::__float_to_tf32(v.z);
        v.w = wmma::__float_to_tf32(v.w);
        ((float4*)g_W32)[idx] = v;
    }
    if (idx < 16 * DMODEL / 4) {
        float4 b = ((const float4*)bias)[idx & (DMODEL / 4 - 1)];
        ((float4*)g_biasrep)[idx] = b;
    }
}

// ---------------------------------------------------------------------------
// GEMM: C[16384,1024] = g_heads(tf32) @ g_W32(tf32) + bias
// Block 128x128, K-tile 32, 8 warps (4Mx2N), warp tile 32x64,
// 3-stage cp.async pipeline. WMMA tf32 m16n16k8.
// R5: NO min-blocks clause — R4's __launch_bounds__(256,2) capped regs at 128
// and likely spilled the fragment set into the inner loop.
// ---------------------------------------------------------------------------
#define GM 16384
#define GN 1024
#define GK 1024
#define BM 128
#define BN 128
#define BK 32
#define NKT (GK / BK)        // 32
#define LDA 36               // padded A smem row (floats)
#define LDB 132              // padded B smem row (floats)
#define A_STG (BM * LDA)     // 4608 floats per stage
#define B_STG (BK * LDB)     // 4224 floats per stage
#define GEMM_SMEM ((3 * (A_STG + B_STG)) * 4)   // 105984 bytes

__global__ __launch_bounds__(256) void gemm_kernel(float* __restrict__ C)
{
    extern __shared__ __align__(16) float smg[];
    const int tid = threadIdx.x;
    const int wid = tid >> 5;
    const int wm  = wid & 3;            // 0..3 (M)
    const int wn  = wid >> 2;           // 0..1 (N)
    const int bm  = blockIdx.y * BM;
    const int bn  = blockIdx.x * BN;

    const float* Ag  = g_heads + (size_t)bm * GK;
    const float* Bgp = g_W32 + bn;

    const uint32_t smem_b = smem_u32(smg);

    // accumulators init from replicated bias (global load)
    wmma::fragment<wmma::accumulator, 16, 16, 8, float> cf[2][4];
#pragma unroll
    for (int i = 0; i < 2; ++i)
#pragma unroll
        for (int j = 0; j < 4; ++j)
            wmma::load_matrix_sync(cf[i][j], g_biasrep + bn + wn * 64 + j * 16,
                                   GN, wmma::mem_row_major);

    // per-thread cp.async source/dest decomposition
    const int arow = tid >> 3;          // 0..31 (+32 per iter), A: 128 rows x 8 f4
    const int acol = (tid & 7) << 2;    // float col 0..28
    const int brow = tid >> 5;          // 0..7 (+8 per iter),  B: 32 rows x 32 f4
    const int bcol = (tid & 31) << 2;

    auto load_stage = [&](int kt, int s) {
        const int kof = kt * BK;
        uint32_t adst = smem_b + (s * A_STG) * 4;
        uint32_t bdst = smem_b + (3 * A_STG + s * B_STG) * 4;
#pragma unroll
        for (int i = 0; i < 4; ++i) {
            const int r = arow + i * 32;
            CP_ASYNC16(adst + (r * LDA + acol) * 4,
                       Ag + (size_t)r * GK + kof + acol);
        }
#pragma unroll
        for (int i = 0; i < 4; ++i) {
            const int r = brow + i * 8;
            CP_ASYNC16(bdst + (r * LDB + bcol) * 4,
                       Bgp + (size_t)(kof + r) * GN + bcol);
        }
    };

    load_stage(0, 0); CP_COMMIT();
    load_stage(1, 1); CP_COMMIT();

    for (int c = 0; c < NKT; ++c) {
        const int s = c % 3;
        CP_WAIT1();
        __syncthreads();
        if (c + 2 < NKT) load_stage(c + 2, (c + 2) % 3);
        CP_COMMIT();

        const float* As = smg + s * A_STG;
        const float* Bs = smg + 3 * A_STG + s * B_STG;
#pragma unroll
        for (int k0 = 0; k0 < BK; k0 += 8) {
            wmma::fragment<wmma::matrix_a, 16, 16, 8, wmma::precision::tf32,
                           wmma::row_major> af[2];
            wmma::fragment<wmma::matrix_b, 16, 16, 8, wmma::precision::tf32,
                           wmma::row_major> bf[4];
#pragma unroll
            for (int i = 0; i < 2; ++i)
                wmma::load_matrix_sync(af[i], As + (wm * 32 + i * 16) * LDA + k0, LDA);
#pragma unroll
            for (int j = 0; j < 4; ++j)
                wmma::load_matrix_sync(bf[j], Bs + k0 * LDB + wn * 64 + j * 16, LDB);
#pragma unroll
            for (int i = 0; i < 2; ++i)
#pragma unroll
                for (int j = 0; j < 4; ++j)
                    wmma::mma_sync(cf[i][j], af[i], bf[j], cf[i][j]);
        }
        __syncthreads();
    }

#pragma unroll
    for (int i = 0; i < 2; ++i)
#pragma unroll
        for (int j = 0; j < 4; ++j)
            wmma::store_matrix_sync(
                C + (size_t)(bm + wm * 32 + i * 16) * GN + bn + wn * 64 + j * 16,
                cf[i][j], GN, wmma::mem_row_major);
}

// ---------------------------------------------------------------------------
extern "C" void kernel_launch(void* const* d_in, const int* in_sizes, int n_in,
                              void* d_out, int out_size)
{
    const float* x    = (const float*)d_in[0];
    const float* Kst  = (const float*)d_in[1];
    const float* Vst  = (const float*)d_in[2];
    const float* Wrt  = (const float*)d_in[3];
    const float* Wout = (const float*)d_in[4];
    const float* bout = (const float*)d_in[5];
    float* out = (float*)d_out;

    const int attn_smem = ATTN_SMEM_FLOATS * (int)sizeof(float);
    cudaFuncSetAttribute(attn_kernel,
                         cudaFuncAttributeMaxDynamicSharedMemorySize, attn_smem);
    cudaFuncSetAttribute(gemm_kernel,
                         cudaFuncAttributeMaxDynamicSharedMemorySize, GEMM_SMEM);

    convert_kernel<<<DMODEL * DMODEL / 4 / 256, 256>>>(Wout, bout);
    attn_kernel<<<dim3(NHEAD, NTOK / TOK_PER_BLK), ATTN_THREADS, attn_smem>>>(
        x, Kst, Vst, Wrt);
    gemm_kernel<<<dim3(GN / BN, GM / BM), 256, GEMM_SMEM>>>(out);
}

// round 6
// speedup vs baseline: 1.5041x; 1.0181x over previous
#include <cuda_runtime.h>
#include <cuda_bf16.h>
#include <mma.h>
#include <math.h>
#include <stdint.h>

using namespace nvcuda;

// Problem constants
#define NTOK   16384      // B*S
#define DMODEL 1024
#define NHEAD  16
#define HD     64
#define NP     32
#define NR     8
#define NPR    256

// Scratch (allocation-free rule)
__device__ float g_heads[(size_t)NTOK * DMODEL];     // tf32-rounded heads
__device__ float g_W32[(size_t)DMODEL * DMODEL];     // tf32-rounded W_out [K,N]
__device__ float g_biasrep[16 * DMODEL];             // bias replicated 16 rows

// ---------------------------------------------------------------------------
__device__ __forceinline__ uint32_t smem_u32(const void* p) {
    uint32_t a;
    asm("{ .reg .u64 t; cvta.to.shared.u64 t, %1; cvt.u32.u64 %0, t; }"
        : "=r"(a) : "l"(p));
    return a;
}
#define CP_ASYNC16(dst, src) \
    asm volatile("cp.async.cg.shared.global [%0], [%1], 16;" :: "r"(dst), "l"(src))
#define CP_COMMIT() asm volatile("cp.async.commit_group;" ::: "memory")
#define CP_WAIT2()  asm volatile("cp.async.wait_group 2;" ::: "memory")

// ---------------------------------------------------------------------------
// Warp reduction helpers
// ---------------------------------------------------------------------------
__device__ __forceinline__ float warp_max(float v) {
#pragma unroll
    for (int o = 16; o > 0; o >>= 1) v = fmaxf(v, __shfl_xor_sync(0xffffffffu, v, o));
    return v;
}
__device__ __forceinline__ float warp_sum(float v) {
#pragma unroll
    for (int o = 16; o > 0; o >>= 1) v += __shfl_xor_sync(0xffffffffu, v, o);
    return v;
}
__device__ __forceinline__ float g8_max(float v) {
#pragma unroll
    for (int o = 4; o > 0; o >>= 1) v = fmaxf(v, __shfl_xor_sync(0xffffffffu, v, o));
    return v;
}
__device__ __forceinline__ float g8_sum(float v) {
#pragma unroll
    for (int o = 4; o > 0; o >>= 1) v += __shfl_xor_sync(0xffffffffu, v, o);
    return v;
}

// ---------------------------------------------------------------------------
// Attention kernel: one block = (head, 512-token chunk), 32 warps.
// R6: float4 xw broadcasts in logits/scores (fewer LDS issues, shorter chains)
// ---------------------------------------------------------------------------
#define ATTN_THREADS 1024
#define ATTN_WARPS   32
#define TOK_PER_BLK  512
#define ATTN_SMEM_FLOATS (2048 + 16384 + 16384 + ATTN_WARPS * 64)

__global__ __launch_bounds__(ATTN_THREADS) void attn_kernel(
    const float* __restrict__ x,
    const float* __restrict__ Kst,
    const float* __restrict__ Vst,
    const float* __restrict__ Wrt)
{
    extern __shared__ float sm[];
    float* Wr_s = sm;                 // [64][32]
    float* Ks   = sm + 2048;          // [64][256]
    float* Vs   = Ks + 16384;         // [256][64]
    float* xs   = Vs + 16384;         // [32][64]

    const int h    = blockIdx.x;
    const int tid  = threadIdx.x;
    const int wid  = tid >> 5;
    const int lane = tid & 31;
    const unsigned FULL = 0xffffffffu;

    for (int i = tid; i < HD * NP; i += ATTN_THREADS)
        Wr_s[i] = Wrt[h * HD * NP + i];
    const float* Kh = Kst + (size_t)h * NPR * HD;
    for (int i = tid; i < NPR * HD; i += ATTN_THREADS) {
        int d = i & 63, pr = i >> 6;
        Ks[d * NPR + pr] = Kh[i];
    }
    const float* Vh = Vst + (size_t)h * NPR * HD;
    for (int i = tid; i < NPR * HD; i += ATTN_THREADS)
        Vs[i] = Vh[i];
    __syncthreads();

    float* xw = xs + wid * 64;
    const int e8 = lane >> 3;
    const int r8 = lane & 7;

    for (int it = 0; it < TOK_PER_BLK / ATTN_WARPS; ++it) {
        const int tk = blockIdx.y * TOK_PER_BLK + it * ATTN_WARPS + wid;
        const float* xp = x + (size_t)tk * DMODEL + h * HD;

        float2 xv = ((const float2*)xp)[lane];
        xw[2 * lane]     = xv.x;
        xw[2 * lane + 1] = xv.y;
        __syncwarp();

        // ---- router logits: float4 broadcast of xw + 4 accumulators ----
        float l0 = 0.f, l1 = 0.f, l2 = 0.f, l3 = 0.f;
#pragma unroll
        for (int d = 0; d < HD; d += 4) {
            const float4 xq = *(const float4*)(xw + d);
            l0 = fmaf(xq.x, Wr_s[d * NP + lane],       l0);
            l1 = fmaf(xq.y, Wr_s[(d + 1) * NP + lane], l1);
            l2 = fmaf(xq.z, Wr_s[(d + 2) * NP + lane], l2);
            l3 = fmaf(xq.w, Wr_s[(d + 3) * NP + lane], l3);
        }
        float lg = (l0 + l1) + (l2 + l3);

        // ---- top-4 threshold ----
        float m0  = warp_max(lg);
        float cur = lg, mm = m0;
#pragma unroll
        for (int i = 0; i < 3; ++i) {
            cur = (cur == mm) ? -INFINITY : cur;
            mm  = warp_max(cur);
        }
        const bool sel = (lg >= mm);
        float ev   = sel ? __expf(lg - m0) : 0.f;
        float gate = ev / warp_sum(ev);

        unsigned bal = __ballot_sync(FULL, sel);
        int pa0, pa1, pa2, pa3;
        {
            unsigned b = bal;
            pa0 = __ffs(b) - 1; b &= b - 1;
            pa1 = __ffs(b) - 1; b &= b - 1;
            pa2 = __ffs(b) - 1; b &= b - 1;
            pa3 = __ffs(b) - 1;
            if (pa0 < 0) pa0 = 0;
            if (pa1 < 0) pa1 = pa0;
            if (pa2 < 0) pa2 = pa1;
            if (pa3 < 0) pa3 = pa2;
        }
        const float ga0 = __shfl_sync(FULL, gate, pa0);
        const float ga1 = __shfl_sync(FULL, gate, pa1);
        const float ga2 = __shfl_sync(FULL, gate, pa2);
        const float ga3 = __shfl_sync(FULL, gate, pa3);

        const int   p_my = (e8 == 0) ? pa0 : (e8 == 1) ? pa1 : (e8 == 2) ? pa2 : pa3;
        const float g_my = (e8 == 0) ? ga0 : (e8 == 1) ? ga1 : (e8 == 2) ? ga2 : ga3;

        // ---- scores: float4 broadcast of xw + 4 accumulators ----
        const float* kc = Ks + p_my * NR + r8;
        float s0 = 0.f, s1 = 0.f, s2 = 0.f, s3 = 0.f;
#pragma unroll
        for (int d = 0; d < HD; d += 4) {
            const float4 xq = *(const float4*)(xw + d);
            s0 = fmaf(xq.x, kc[d * NPR],       s0);
            s1 = fmaf(xq.y, kc[(d + 1) * NPR], s1);
            s2 = fmaf(xq.z, kc[(d + 2) * NPR], s2);
            s3 = fmaf(xq.w, kc[(d + 3) * NPR], s3);
        }
        float sc = ((s0 + s1) + (s2 + s3)) * 0.125f;

        const float sm8 = g8_max(sc);
        const float ex  = __expf(sc - sm8);
        const float wv  = (ex / g8_sum(ex)) * g_my;

        // ---- combine: lane owns dims (2*lane, 2*lane+1); float2 LDS ----
        float a0x = 0.f, a0y = 0.f, a1x = 0.f, a1y = 0.f;
#pragma unroll
        for (int j = 0; j < 32; j += 2) {
            const float wj0 = __shfl_sync(FULL, wv, j);
            const float wj1 = __shfl_sync(FULL, wv, j + 1);
            const int pj0 = (j < 8) ? pa0 : (j < 16) ? pa1 : (j < 24) ? pa2 : pa3;
            const int jb  = j + 1;
            const int pj1 = (jb < 8) ? pa0 : (jb < 16) ? pa1 : (jb < 24) ? pa2 : pa3;
            const float2 v0 = ((const float2*)(Vs + (pj0 * NR + (j & 7)) * HD))[lane];
            const float2 v1 = ((const float2*)(Vs + (pj1 * NR + (jb & 7)) * HD))[lane];
            a0x = fmaf(wj0, v0.x, a0x);
            a0y = fmaf(wj0, v0.y, a0y);
            a1x = fmaf(wj1, v1.x, a1x);
            a1y = fmaf(wj1, v1.y, a1y);
        }

        // store tf32-rounded so GEMM can consume raw bits
        float2 o2;
        o2.x = wmma::__float_to_tf32(a0x + a1x);
        o2.y = wmma::__float_to_tf32(a0y + a1y);
        *(float2*)(g_heads + (size_t)tk * DMODEL + h * HD + 2 * lane) = o2;
        __syncwarp();
    }
}

// ---------------------------------------------------------------------------
// Convert W_out -> tf32 and replicate bias into 16 rows
// ---------------------------------------------------------------------------
__global__ __launch_bounds__(256) void convert_kernel(
    const float* __restrict__ W, const float* __restrict__ bias)
{
    const int idx = blockIdx.x * 256 + threadIdx.x;           // float4 index
    const int n4 = DMODEL * DMODEL / 4;                       // 262144
    if (idx < n4) {
        float4 v = ((const float4*)W)[idx];
        v.x = wmma::__float_to_tf32(v.x);
        v.y = wmma::__float_to_tf32(v.y);
        v.z = wmma::__float_to_tf32(v.z);
        v.w = wmma::__float_to_tf32(v.w);
        ((float4*)g_W32)[idx] = v;
    }
    if (idx < 16 * DMODEL / 4) {
        float4 b = ((const float4*)bias)[idx & (DMODEL / 4 - 1)];
        ((float4*)g_biasrep)[idx] = b;
    }
}

// ---------------------------------------------------------------------------
// GEMM: C[16384,1024] = g_heads(tf32) @ g_W32(tf32) + bias
// Block 128x128, K-tile 32, 8 warps (4Mx2N), warp tile 32x64.
// R6: 4-stage cp.async pipeline, wait_group 2 (two tile-loads in flight
// during compute), single barrier per k-tile.
// ---------------------------------------------------------------------------
#define GM 16384
#define GN 1024
#define GK 1024
#define BM 128
#define BN 128
#define BK 32
#define NKT (GK / BK)        // 32
#define STG 4
#define LDA 36               // padded A smem row (floats)
#define LDB 132              // padded B smem row (floats)
#define A_STG (BM * LDA)     // 4608 floats per stage
#define B_STG (BK * LDB)     // 4224 floats per stage
#define GEMM_SMEM ((STG * (A_STG + B_STG)) * 4)   // 141312 bytes

__global__ __launch_bounds__(256) void gemm_kernel(float* __restrict__ C)
{
    extern __shared__ __align__(16) float smg[];
    const int tid = threadIdx.x;
    const int wid = tid >> 5;
    const int wm  = wid & 3;            // 0..3 (M)
    const int wn  = wid >> 2;           // 0..1 (N)
    const int bm  = blockIdx.y * BM;
    const int bn  = blockIdx.x * BN;

    const float* Ag  = g_heads + (size_t)bm * GK;
    const float* Bgp = g_W32 + bn;

    const uint32_t smem_b = smem_u32(smg);

    // accumulators init from replicated bias (global load)
    wmma::fragment<wmma::accumulator, 16, 16, 8, float> cf[2][4];
#pragma unroll
    for (int i = 0; i < 2; ++i)
#pragma unroll
        for (int j = 0; j < 4; ++j)
            wmma::load_matrix_sync(cf[i][j], g_biasrep + bn + wn * 64 + j * 16,
                                   GN, wmma::mem_row_major);

    // per-thread cp.async source/dest decomposition
    const int arow = tid >> 3;          // 0..31 (+32 per iter), A: 128 rows x 8 f4
    const int acol = (tid & 7) << 2;    // float col 0..28
    const int brow = tid >> 5;          // 0..7 (+8 per iter),  B: 32 rows x 32 f4
    const int bcol = (tid & 31) << 2;

    auto load_stage = [&](int kt, int s) {
        const int kof = kt * BK;
        uint32_t adst = smem_b + (s * A_STG) * 4;
        uint32_t bdst = smem_b + (STG * A_STG + s * B_STG) * 4;
#pragma unroll
        for (int i = 0; i < 4; ++i) {
            const int r = arow + i * 32;
            CP_ASYNC16(adst + (r * LDA + acol) * 4,
                       Ag + (size_t)r * GK + kof + acol);
        }
#pragma unroll
        for (int i = 0; i < 4; ++i) {
            const int r = brow + i * 8;
            CP_ASYNC16(bdst + (r * LDB + bcol) * 4,
                       Bgp + (size_t)(kof + r) * GN + bcol);
        }
    };

    load_stage(0, 0); CP_COMMIT();
    load_stage(1, 1); CP_COMMIT();
    load_stage(2, 2); CP_COMMIT();

    for (int c = 0; c < NKT; ++c) {
        const int s = c & 3;
        CP_WAIT2();                      // group c complete (<=2 newer pending)
        __syncthreads();                 // all threads' stage-c data visible
        if (c + 3 < NKT) load_stage(c + 3, (c + 3) & 3);
        CP_COMMIT();                     // keep group numbering (empty ok)

        const float* As = smg + s * A_STG;
        const float* Bs = smg + STG * A_STG + s * B_STG;
#pragma unroll
        for (int k0 = 0; k0 < BK; k0 += 8) {
            wmma::fragment<wmma::matrix_a, 16, 16, 8, wmma::precision::tf32,
                           wmma::row_major> af[2];
            wmma::fragment<wmma::matrix_b, 16, 16, 8, wmma::precision::tf32,
                           wmma::row_major> bf[4];
#pragma unroll
            for (int i = 0; i < 2; ++i)
                wmma::load_matrix_sync(af[i], As + (wm * 32 + i * 16) * LDA + k0, LDA);
#pragma unroll
            for (int j = 0; j < 4; ++j)
                wmma::load_matrix_sync(bf[j], Bs + k0 * LDB + wn * 64 + j * 16, LDB);
#pragma unroll
            for (int i = 0; i < 2; ++i)
#pragma unroll
                for (int j = 0; j < 4; ++j)
                    wmma::mma_sync(cf[i][j], af[i], bf[j], cf[i][j]);
        }
    }

#pragma unroll
    for (int i = 0; i < 2; ++i)
#pragma unroll
        for (int j = 0; j < 4; ++j)
            wmma::store_matrix_sync(
                C + (size_t)(bm + wm * 32 + i * 16) * GN + bn + wn * 64 + j * 16,
                cf[i][j], GN, wmma::mem_row_major);
}

// ---------------------------------------------------------------------------
extern "C" void kernel_launch(void* const* d_in, const int* in_sizes, int n_in,
                              void* d_out, int out_size)
{
    const float* x    = (const float*)d_in[0];
    const float* Kst  = (const float*)d_in[1];
    const float* Vst  = (const float*)d_in[2];
    const float* Wrt  = (const float*)d_in[3];
    const float* Wout = (const float*)d_in[4];
    const float* bout = (const float*)d_in[5];
    float* out = (float*)d_out;

    const int attn_smem = ATTN_SMEM_FLOATS * (int)sizeof(float);
    cudaFuncSetAttribute(attn_kernel,
                         cudaFuncAttributeMaxDynamicSharedMemorySize, attn_smem);
    cudaFuncSetAttribute(gemm_kernel,
                         cudaFuncAttributeMaxDynamicSharedMemorySize, GEMM_SMEM);

    // attn first (diagnostic: ncu samples the first kernel of a replay)
    attn_kernel<<<dim3(NHEAD, NTOK / TOK_PER_BLK), ATTN_THREADS, attn_smem>>>(
        x, Kst, Vst, Wrt);
    convert_kernel<<<DMODEL * DMODEL / 4 / 256, 256>>>(Wout, bout);
    gemm_kernel<<<dim3(GN / BN, GM / BM), 256, GEMM_SMEM>>>(out);
}

// round 7
// speedup vs baseline: 1.7430x; 1.1588x over previous
#include <cuda_runtime.h>
#include <cuda_bf16.h>
#include <mma.h>
#include <math.h>
#include <stdint.h>

using namespace nvcuda;

// Problem constants
#define NTOK   16384      // B*S
#define DMODEL 1024
#define NHEAD  16
#define HD     64
#define NP     32
#define NR     8
#define NPR    256

// Scratch (allocation-free rule)
__device__ float g_heads[(size_t)NTOK * DMODEL];     // tf32-rounded heads
__device__ float g_W32[(size_t)DMODEL * DMODEL];     // tf32-rounded W_out [K,N]
__device__ float g_biasrep[16 * DMODEL];             // bias replicated 16 rows

// ---------------------------------------------------------------------------
__device__ __forceinline__ uint32_t smem_u32(const void* p) {
    uint32_t a;
    asm("{ .reg .u64 t; cvta.to.shared.u64 t, %1; cvt.u32.u64 %0, t; }"
        : "=r"(a) : "l"(p));
    return a;
}
#define CP_ASYNC16(dst, src) \
    asm volatile("cp.async.cg.shared.global [%0], [%1], 16;" :: "r"(dst), "l"(src))
#define CP_COMMIT() asm volatile("cp.async.commit_group;" ::: "memory")
#define CP_WAIT1()  asm volatile("cp.async.wait_group 1;" ::: "memory")

// ---------------------------------------------------------------------------
// Warp reduction helpers
// ---------------------------------------------------------------------------
__device__ __forceinline__ float warp_max(float v) {
#pragma unroll
    for (int o = 16; o > 0; o >>= 1) v = fmaxf(v, __shfl_xor_sync(0xffffffffu, v, o));
    return v;
}
__device__ __forceinline__ float warp_sum(float v) {
#pragma unroll
    for (int o = 16; o > 0; o >>= 1) v += __shfl_xor_sync(0xffffffffu, v, o);
    return v;
}
__device__ __forceinline__ float g8_max(float v) {
#pragma unroll
    for (int o = 4; o > 0; o >>= 1) v = fmaxf(v, __shfl_xor_sync(0xffffffffu, v, o));
    return v;
}
__device__ __forceinline__ float g8_sum(float v) {
#pragma unroll
    for (int o = 4; o > 0; o >>= 1) v += __shfl_xor_sync(0xffffffffu, v, o);
    return v;
}

// ---------------------------------------------------------------------------
// Attention kernel: one block = (head, 512-token chunk), 32 warps.
// R7: K stored row-major [pr][68] (272B rows). Score reads are float4 with
// phase = one expert's 8 slots -> 16B-groups (r+d) mod 8 all distinct ->
// conflict-free regardless of selected experts.
// ---------------------------------------------------------------------------
#define ATTN_THREADS 1024
#define ATTN_WARPS   32
#define TOK_PER_BLK  512
#define KROW 68
// Wr 2048 | Ks 256*68=17408 | Vs 16384 | xs 32*64=2048
#define ATTN_SMEM_FLOATS (2048 + NPR * KROW + 16384 + ATTN_WARPS * 64)

__global__ __launch_bounds__(ATTN_THREADS) void attn_kernel(
    const float* __restrict__ x,
    const float* __restrict__ Kst,
    const float* __restrict__ Vst,
    const float* __restrict__ Wrt)
{
    extern __shared__ float sm[];
    float* Wr_s = sm;                     // [64][32]
    float* Ks   = sm + 2048;              // [256][68]
    float* Vs   = Ks + NPR * KROW;        // [256][64]
    float* xs   = Vs + 16384;             // [32][64]

    const int h    = blockIdx.x;
    const int tid  = threadIdx.x;
    const int wid  = tid >> 5;
    const int lane = tid & 31;
    const unsigned FULL = 0xffffffffu;

    for (int i = tid; i < HD * NP; i += ATTN_THREADS)
        Wr_s[i] = Wrt[h * HD * NP + i];
    const float* Kh = Kst + (size_t)h * NPR * HD;
    for (int i = tid; i < NPR * HD; i += ATTN_THREADS) {
        int d = i & 63, pr = i >> 6;
        Ks[pr * KROW + d] = Kh[i];        // row-major, padded rows
    }
    const float* Vh = Vst + (size_t)h * NPR * HD;
    for (int i = tid; i < NPR * HD; i += ATTN_THREADS)
        Vs[i] = Vh[i];
    __syncthreads();

    float* xw = xs + wid * 64;
    const int e8 = lane >> 3;
    const int r8 = lane & 7;

    for (int it = 0; it < TOK_PER_BLK / ATTN_WARPS; ++it) {
        const int tk = blockIdx.y * TOK_PER_BLK + it * ATTN_WARPS + wid;
        const float* xp = x + (size_t)tk * DMODEL + h * HD;

        float2 xv = ((const float2*)xp)[lane];
        xw[2 * lane]     = xv.x;
        xw[2 * lane + 1] = xv.y;
        __syncwarp();

        // ---- router logits: float4 broadcast of xw + 4 accumulators ----
        float l0 = 0.f, l1 = 0.f, l2 = 0.f, l3 = 0.f;
#pragma unroll
        for (int d = 0; d < HD; d += 4) {
            const float4 xq = *(const float4*)(xw + d);
            l0 = fmaf(xq.x, Wr_s[d * NP + lane],       l0);
            l1 = fmaf(xq.y, Wr_s[(d + 1) * NP + lane], l1);
            l2 = fmaf(xq.z, Wr_s[(d + 2) * NP + lane], l2);
            l3 = fmaf(xq.w, Wr_s[(d + 3) * NP + lane], l3);
        }
        float lg = (l0 + l1) + (l2 + l3);

        // ---- top-4 threshold ----
        float m0  = warp_max(lg);
        float cur = lg, mm = m0;
#pragma unroll
        for (int i = 0; i < 3; ++i) {
            cur = (cur == mm) ? -INFINITY : cur;
            mm  = warp_max(cur);
        }
        const bool sel = (lg >= mm);
        float ev   = sel ? __expf(lg - m0) : 0.f;
        float gate = ev / warp_sum(ev);

        unsigned bal = __ballot_sync(FULL, sel);
        int pa0, pa1, pa2, pa3;
        {
            unsigned b = bal;
            pa0 = __ffs(b) - 1; b &= b - 1;
            pa1 = __ffs(b) - 1; b &= b - 1;
            pa2 = __ffs(b) - 1; b &= b - 1;
            pa3 = __ffs(b) - 1;
            if (pa0 < 0) pa0 = 0;
            if (pa1 < 0) pa1 = pa0;
            if (pa2 < 0) pa2 = pa1;
            if (pa3 < 0) pa3 = pa2;
        }
        const float ga0 = __shfl_sync(FULL, gate, pa0);
        const float ga1 = __shfl_sync(FULL, gate, pa1);
        const float ga2 = __shfl_sync(FULL, gate, pa2);
        const float ga3 = __shfl_sync(FULL, gate, pa3);

        const int   p_my = (e8 == 0) ? pa0 : (e8 == 1) ? pa1 : (e8 == 2) ? pa2 : pa3;
        const float g_my = (e8 == 0) ? ga0 : (e8 == 1) ? ga1 : (e8 == 2) ? ga2 : ga3;

        // ---- scores: conflict-free float4 row reads of K ----
        const float* kr = Ks + (p_my * NR + r8) * KROW;
        float s0 = 0.f, s1 = 0.f, s2 = 0.f, s3 = 0.f;
#pragma unroll
        for (int d = 0; d < HD; d += 4) {
            const float4 xq = *(const float4*)(xw + d);
            const float4 kq = *(const float4*)(kr + d);
            s0 = fmaf(xq.x, kq.x, s0);
            s1 = fmaf(xq.y, kq.y, s1);
            s2 = fmaf(xq.z, kq.z, s2);
            s3 = fmaf(xq.w, kq.w, s3);
        }
        float sc = ((s0 + s1) + (s2 + s3)) * 0.125f;

        const float sm8 = g8_max(sc);
        const float ex  = __expf(sc - sm8);
        const float wv  = (ex / g8_sum(ex)) * g_my;

        // ---- combine: lane owns dims (2*lane, 2*lane+1); float2 LDS ----
        float a0x = 0.f, a0y = 0.f, a1x = 0.f, a1y = 0.f;
#pragma unroll
        for (int j = 0; j < 32; j += 2) {
            const float wj0 = __shfl_sync(FULL, wv, j);
            const float wj1 = __shfl_sync(FULL, wv, j + 1);
            const int pj0 = (j < 8) ? pa0 : (j < 16) ? pa1 : (j < 24) ? pa2 : pa3;
            const int jb  = j + 1;
            const int pj1 = (jb < 8) ? pa0 : (jb < 16) ? pa1 : (jb < 24) ? pa2 : pa3;
            const float2 v0 = ((const float2*)(Vs + (pj0 * NR + (j & 7)) * HD))[lane];
            const float2 v1 = ((const float2*)(Vs + (pj1 * NR + (jb & 7)) * HD))[lane];
            a0x = fmaf(wj0, v0.x, a0x);
            a0y = fmaf(wj0, v0.y, a0y);
            a1x = fmaf(wj1, v1.x, a1x);
            a1y = fmaf(wj1, v1.y, a1y);
        }

        float2 o2;
        o2.x = wmma::__float_to_tf32(a0x + a1x);
        o2.y = wmma::__float_to_tf32(a0y + a1y);
        *(float2*)(g_heads + (size_t)tk * DMODEL + h * HD + 2 * lane) = o2;
        __syncwarp();
    }
}

// ---------------------------------------------------------------------------
// Convert W_out -> tf32 and replicate bias into 16 rows
// ---------------------------------------------------------------------------
__global__ __launch_bounds__(256) void convert_kernel(
    const float* __restrict__ W, const float* __restrict__ bias)
{
    const int idx = blockIdx.x * 256 + threadIdx.x;           // float4 index
    const int n4 = DMODEL * DMODEL / 4;                       // 262144
    if (idx < n4) {
        float4 v = ((const float4*)W)[idx];
        v.x = wmma::__float_to_tf32(v.x);
        v.y = wmma::__float_to_tf32(v.y);
        v.z = wmma::__float_to_tf32(v.z);
        v.w = wmma::__float_to_tf32(v.w);
        ((float4*)g_W32)[idx] = v;
    }
    if (idx < 16 * DMODEL / 4) {
        float4 b = ((const float4*)bias)[idx & (DMODEL / 4 - 1)];
        ((float4*)g_biasrep)[idx] = b;
    }
}

// ---------------------------------------------------------------------------
// GEMM: C[16384,1024] = g_heads(tf32) @ g_W32(tf32) + bias
// R7: warp tile 64x64 (4 warps, 128 threads), block 128x128x32,
// 3-stage cp.async (106KB smem -> 2 CTAs/SM). Frag-load bytes per FLOP
// halved vs 32x64 warp tile.
// ---------------------------------------------------------------------------
#define GM 16384
#define GN 1024
#define GK 1024
#define BM 128
#define BN 128
#define BK 32
#define NKT (GK / BK)        // 32
#define STG 3
#define LDA 36               // padded A smem row (floats)
#define LDB 132              // padded B smem row (floats)
#define A_STG (BM * LDA)     // 4608 floats per stage
#define B_STG (BK * LDB)     // 4224 floats per stage
#define GEMM_SMEM ((STG * (A_STG + B_STG)) * 4)   // 105984 bytes

__global__ __launch_bounds__(128) void gemm_kernel(float* __restrict__ C)
{
    extern __shared__ __align__(16) float smg[];
    const int tid = threadIdx.x;
    const int wid = tid >> 5;
    const int wm  = wid & 1;            // 0..1 (M)
    const int wn  = wid >> 1;           // 0..1 (N)
    const int bm  = blockIdx.y * BM;
    const int bn  = blockIdx.x * BN;

    const float* Ag  = g_heads + (size_t)bm * GK;
    const float* Bgp = g_W32 + bn;

    const uint32_t smem_b = smem_u32(smg);

    // accumulators init from replicated bias (global load)
    wmma::fragment<wmma::accumulator, 16, 16, 8, float> cf[4][4];
#pragma unroll
    for (int i = 0; i < 4; ++i)
#pragma unroll
        for (int j = 0; j < 4; ++j)
            wmma::load_matrix_sync(cf[i][j], g_biasrep + bn + wn * 64 + j * 16,
                                   GN, wmma::mem_row_major);

    // cp.async decomposition (128 threads)
    const int arow = tid >> 3;          // 0..15 (+16/pass), A: 128 rows x 8 f4
    const int acol = (tid & 7) << 2;    // float col 0,4,..,28
    const int brow = tid >> 5;          // 0..3 (+4/pass),  B: 32 rows x 32 f4
    const int bcol = (tid & 31) << 2;

    auto load_stage = [&](int kt, int s) {
        const int kof = kt * BK;
        uint32_t adst = smem_b + (s * A_STG) * 4;
        uint32_t bdst = smem_b + (STG * A_STG + s * B_STG) * 4;
#pragma unroll
        for (int i = 0; i < 8; ++i) {
            const int r = arow + i * 16;
            CP_ASYNC16(adst + (r * LDA + acol) * 4,
                       Ag + (size_t)r * GK + kof + acol);
        }
#pragma unroll
        for (int i = 0; i < 8; ++i) {
            const int r = brow + i * 4;
            CP_ASYNC16(bdst + (r * LDB + bcol) * 4,
                       Bgp + (size_t)(kof + r) * GN + bcol);
        }
    };

    load_stage(0, 0); CP_COMMIT();
    load_stage(1, 1); CP_COMMIT();

    for (int c = 0; c < NKT; ++c) {
        const int s = c % 3;
        CP_WAIT1();                      // stage c complete (<=1 newer pending)
        __syncthreads();                 // everyone done reading stage (c-1)%3
        if (c + 2 < NKT) load_stage(c + 2, (c + 2) % 3);
        CP_COMMIT();

        const float* As = smg + s * A_STG;
        const float* Bs = smg + STG * A_STG + s * B_STG;
#pragma unroll
        for (int k0 = 0; k0 < BK; k0 += 8) {
            wmma::fragment<wmma::matrix_a, 16, 16, 8, wmma::precision::tf32,
                           wmma::row_major> af[4];
            wmma::fragment<wmma::matrix_b, 16, 16, 8, wmma::precision::tf32,
                           wmma::row_major> bf[4];
#pragma unroll
            for (int i = 0; i < 4; ++i)
                wmma::load_matrix_sync(af[i], As + (wm * 64 + i * 16) * LDA + k0, LDA);
#pragma unroll
            for (int j = 0; j < 4; ++j)
                wmma::load_matrix_sync(bf[j], Bs + k0 * LDB + wn * 64 + j * 16, LDB);
#pragma unroll
            for (int i = 0; i < 4; ++i)
#pragma unroll
                for (int j = 0; j < 4; ++j)
                    wmma::mma_sync(cf[i][j], af[i], bf[j], cf[i][j]);
        }
    }

#pragma unroll
    for (int i = 0; i < 4; ++i)
#pragma unroll
        for (int j = 0; j < 4; ++j)
            wmma::store_matrix_sync(
                C + (size_t)(bm + wm * 64 + i * 16) * GN + bn + wn * 64 + j * 16,
                cf[i][j], GN, wmma::mem_row_major);
}

// ---------------------------------------------------------------------------
extern "C" void kernel_launch(void* const* d_in, const int* in_sizes, int n_in,
                              void* d_out, int out_size)
{
    const float* x    = (const float*)d_in[0];
    const float* Kst  = (const float*)d_in[1];
    const float* Vst  = (const float*)d_in[2];
    const float* Wrt  = (const float*)d_in[3];
    const float* Wout = (const float*)d_in[4];
    const float* bout = (const float*)d_in[5];
    float* out = (float*)d_out;

    const int attn_smem = ATTN_SMEM_FLOATS * (int)sizeof(float);   // 151552 B
    cudaFuncSetAttribute(attn_kernel,
                         cudaFuncAttributeMaxDynamicSharedMemorySize, attn_smem);
    cudaFuncSetAttribute(gemm_kernel,
                         cudaFuncAttributeMaxDynamicSharedMemorySize, GEMM_SMEM);

    attn_kernel<<<dim3(NHEAD, NTOK / TOK_PER_BLK), ATTN_THREADS, attn_smem>>>(
        x, Kst, Vst, Wrt);
    convert_kernel<<<DMODEL * DMODEL / 4 / 256, 256>>>(Wout, bout);
    gemm_kernel<<<dim3(GN / BN, GM / BM), 128, GEMM_SMEM>>>(out);
}

// round 8
// speedup vs baseline: 2.9420x; 1.6879x over previous
#include <cuda_runtime.h>
#include <cuda_fp16.h>
#include <mma.h>
#include <math.h>
#include <stdint.h>

using namespace nvcuda;

// Problem constants
#define NTOK   16384      // B*S
#define DMODEL 1024
#define NHEAD  16
#define HD     64
#define NP     32
#define NR     8
#define NPR    256

// Scratch (allocation-free rule)
__device__ __half g_headsh[(size_t)NTOK * DMODEL];   // fp16 heads
__device__ __half g_Wh[(size_t)DMODEL * DMODEL];     // fp16 W_out [K,N]
__device__ float  g_biasrep[16 * DMODEL];            // bias replicated 16 rows

// ---------------------------------------------------------------------------
__device__ __forceinline__ uint32_t smem_u32(const void* p) {
    uint32_t a;
    asm("{ .reg .u64 t; cvta.to.shared.u64 t, %1; cvt.u32.u64 %0, t; }"
        : "=r"(a) : "l"(p));
    return a;
}
#define CP_ASYNC16(dst, src) \
    asm volatile("cp.async.cg.shared.global [%0], [%1], 16;" :: "r"(dst), "l"(src))
#define CP_COMMIT() asm volatile("cp.async.commit_group;" ::: "memory")
#define CP_WAIT1()  asm volatile("cp.async.wait_group 1;" ::: "memory")

// ---------------------------------------------------------------------------
// Warp reduction helpers
// ---------------------------------------------------------------------------
__device__ __forceinline__ float warp_max(float v) {
#pragma unroll
    for (int o = 16; o > 0; o >>= 1) v = fmaxf(v, __shfl_xor_sync(0xffffffffu, v, o));
    return v;
}
__device__ __forceinline__ float warp_sum(float v) {
#pragma unroll
    for (int o = 16; o > 0; o >>= 1) v += __shfl_xor_sync(0xffffffffu, v, o);
    return v;
}
__device__ __forceinline__ float g8_max(float v) {
#pragma unroll
    for (int o = 4; o > 0; o >>= 1) v = fmaxf(v, __shfl_xor_sync(0xffffffffu, v, o));
    return v;
}
__device__ __forceinline__ float g8_sum(float v) {
#pragma unroll
    for (int o = 4; o > 0; o >>= 1) v += __shfl_xor_sync(0xffffffffu, v, o);
    return v;
}

// ---------------------------------------------------------------------------
// Attention kernel: one block = (head, 512-token chunk), 32 warps.
// R8: logits phase-separated per 128-token chunk:
//   Phase F: stage x into d-major xT[64][132] with XOR-by-(d>>3) col swizzle
//            (conflict-free STS, 16B-aligned float4 broadcast reads)
//   Phase A: warp computes 4 tokens x 32 experts: per dim 1 Wr LDS + 1
//            float4 broadcast -> ~34 wf/token incl fill (was 80 inline)
//   Phase B: per-token top-k/softmax/scores/combine, logit = 1 LDS read.
// ---------------------------------------------------------------------------
#define ATTN_THREADS 1024
#define ATTN_WARPS   32
#define TOK_PER_BLK  512
#define CHUNK 128
#define KROW 68
#define XTROW 132
// Wr 2048 | Ks 256*68 | Vs 16384 | xT 64*132 | lg 128*32 | xs 32*64
#define ATTN_SMEM_FLOATS (2048 + NPR * KROW + 16384 + 64 * XTROW + CHUNK * 32 + ATTN_WARPS * 64)

__global__ __launch_bounds__(ATTN_THREADS) void attn_kernel(
    const float* __restrict__ x,
    const float* __restrict__ Kst,
    const float* __restrict__ Vst,
    const float* __restrict__ Wrt)
{
    extern __shared__ float sm[];
    float* Wr_s = sm;                     // [64][32]
    float* Ks   = sm + 2048;              // [256][68]
    float* Vs   = Ks + NPR * KROW;        // [256][64]
    float* xT   = Vs + 16384;             // [64][132] swizzled
    float* lg_s = xT + 64 * XTROW;        // [128][32]
    float* xs   = lg_s + CHUNK * 32;      // [32][64]

    const int h    = blockIdx.x;
    const int tid  = threadIdx.x;
    const int wid  = tid >> 5;
    const int lane = tid & 31;
    const unsigned FULL = 0xffffffffu;

    for (int i = tid; i < HD * NP; i += ATTN_THREADS)
        Wr_s[i] = Wrt[h * HD * NP + i];
    const float* Kh = Kst + (size_t)h * NPR * HD;
    for (int i = tid; i < NPR * HD; i += ATTN_THREADS) {
        int d = i & 63, pr = i >> 6;
        Ks[pr * KROW + d] = Kh[i];        // row-major, padded rows
    }
    const float* Vh = Vst + (size_t)h * NPR * HD;
    for (int i = tid; i < NPR * HD; i += ATTN_THREADS)
        Vs[i] = Vh[i];
    __syncthreads();

    float* xw = xs + wid * 64;
    const int e8 = lane >> 3;
    const int r8 = lane & 7;

    // fill decomposition: tok_local = tid>>3 (0..127), j = tid&7 (d-group)
    const int f_tok = tid >> 3;
    const int f_j   = tid & 7;
    const int f_col = ((f_tok & ~3) ^ (f_j << 2)) | (f_tok & 3);

    const int blockbase = blockIdx.y * TOK_PER_BLK;

    for (int cc = 0; cc < TOK_PER_BLK / CHUNK; ++cc) {
        // ---- Phase F: stage x chunk into swizzled d-major xT ----
        {
            const int tk = blockbase + cc * CHUNK + f_tok;
            const float4* gx = (const float4*)(x + (size_t)tk * DMODEL + h * HD);
            float4 v0 = gx[f_j * 2];
            float4 v1 = gx[f_j * 2 + 1];
            float* dst = xT + (8 * f_j) * XTROW + f_col;
            dst[0 * XTROW] = v0.x; dst[1 * XTROW] = v0.y;
            dst[2 * XTROW] = v0.z; dst[3 * XTROW] = v0.w;
            dst[4 * XTROW] = v1.x; dst[5 * XTROW] = v1.y;
            dst[6 * XTROW] = v1.z; dst[7 * XTROW] = v1.w;
        }
        __syncthreads();

        // ---- Phase A: logits for 4 tokens per warp (lane = expert) ----
        {
            float a0 = 0.f, a1 = 0.f, a2 = 0.f, a3 = 0.f;
#pragma unroll
            for (int d = 0; d < HD; ++d) {
                const float wr = Wr_s[d * NP + lane];
                const int col4 = (4 * wid) ^ (((d >> 3)) << 2);
                const float4 xv = *(const float4*)(xT + d * XTROW + col4);
                a0 = fmaf(xv.x, wr, a0);
                a1 = fmaf(xv.y, wr, a1);
                a2 = fmaf(xv.z, wr, a2);
                a3 = fmaf(xv.w, wr, a3);
            }
            lg_s[(4 * wid + 0) * 32 + lane] = a0;
            lg_s[(4 * wid + 1) * 32 + lane] = a1;
            lg_s[(4 * wid + 2) * 32 + lane] = a2;
            lg_s[(4 * wid + 3) * 32 + lane] = a3;
        }
        __syncthreads();

        // ---- Phase B: 4 tokens per warp, full attention ----
        for (int it2 = 0; it2 < CHUNK / ATTN_WARPS; ++it2) {
            const int tok_local = it2 * ATTN_WARPS + wid;
            const int tk = blockbase + cc * CHUNK + tok_local;
            const float* xp = x + (size_t)tk * DMODEL + h * HD;

            float2 xv = ((const float2*)xp)[lane];
            xw[2 * lane]     = xv.x;
            xw[2 * lane + 1] = xv.y;
            __syncwarp();

            const float lg = lg_s[tok_local * 32 + lane];

            // ---- top-4 threshold ----
            float m0  = warp_max(lg);
            float cur = lg, mm = m0;
#pragma unroll
            for (int i = 0; i < 3; ++i) {
                cur = (cur == mm) ? -INFINITY : cur;
                mm  = warp_max(cur);
            }
            const bool sel = (lg >= mm);
            float ev   = sel ? __expf(lg - m0) : 0.f;
            float gate = ev / warp_sum(ev);

            unsigned bal = __ballot_sync(FULL, sel);
            int pa0, pa1, pa2, pa3;
            {
                unsigned b = bal;
                pa0 = __ffs(b) - 1; b &= b - 1;
                pa1 = __ffs(b) - 1; b &= b - 1;
                pa2 = __ffs(b) - 1; b &= b - 1;
                pa3 = __ffs(b) - 1;
                if (pa0 < 0) pa0 = 0;
                if (pa1 < 0) pa1 = pa0;
                if (pa2 < 0) pa2 = pa1;
                if (pa3 < 0) pa3 = pa2;
            }
            const float ga0 = __shfl_sync(FULL, gate, pa0);
            const float ga1 = __shfl_sync(FULL, gate, pa1);
            const float ga2 = __shfl_sync(FULL, gate, pa2);
            const float ga3 = __shfl_sync(FULL, gate, pa3);

            const int   p_my = (e8 == 0) ? pa0 : (e8 == 1) ? pa1 : (e8 == 2) ? pa2 : pa3;
            const float g_my = (e8 == 0) ? ga0 : (e8 == 1) ? ga1 : (e8 == 2) ? ga2 : ga3;

            // ---- scores: conflict-free float4 row reads of K ----
            const float* kr = Ks + (p_my * NR + r8) * KROW;
            float s0 = 0.f, s1 = 0.f, s2 = 0.f, s3 = 0.f;
#pragma unroll
            for (int d = 0; d < HD; d += 4) {
                const float4 xq = *(const float4*)(xw + d);
                const float4 kq = *(const float4*)(kr + d);
                s0 = fmaf(xq.x, kq.x, s0);
                s1 = fmaf(xq.y, kq.y, s1);
                s2 = fmaf(xq.z, kq.z, s2);
                s3 = fmaf(xq.w, kq.w, s3);
            }
            float sc = ((s0 + s1) + (s2 + s3)) * 0.125f;

            const float sm8 = g8_max(sc);
            const float ex  = __expf(sc - sm8);
            const float wv  = (ex / g8_sum(ex)) * g_my;

            // ---- combine: lane owns dims (2*lane, 2*lane+1) ----
            float a0x = 0.f, a0y = 0.f, a1x = 0.f, a1y = 0.f;
#pragma unroll
            for (int j = 0; j < 32; j += 2) {
                const float wj0 = __shfl_sync(FULL, wv, j);
                const float wj1 = __shfl_sync(FULL, wv, j + 1);
                const int pj0 = (j < 8) ? pa0 : (j < 16) ? pa1 : (j < 24) ? pa2 : pa3;
                const int jb  = j + 1;
                const int pj1 = (jb < 8) ? pa0 : (jb < 16) ? pa1 : (jb < 24) ? pa2 : pa3;
                const float2 v0 = ((const float2*)(Vs + (pj0 * NR + (j & 7)) * HD))[lane];
                const float2 v1 = ((const float2*)(Vs + (pj1 * NR + (jb & 7)) * HD))[lane];
                a0x = fmaf(wj0, v0.x, a0x);
                a0y = fmaf(wj0, v0.y, a0y);
                a1x = fmaf(wj1, v1.x, a1x);
                a1y = fmaf(wj1, v1.y, a1y);
            }

            // store fp16 heads
            __half2 hh = __floats2half2_rn(a0x + a1x, a0y + a1y);
            ((__half2*)(g_headsh + (size_t)tk * DMODEL + h * HD))[lane] = hh;
            __syncwarp();
        }
        __syncthreads();   // lg_s/xT reuse safety for next chunk
    }
}

// ---------------------------------------------------------------------------
// Convert W_out -> fp16 and replicate bias into 16 rows
// ---------------------------------------------------------------------------
__global__ __launch_bounds__(256) void convert_kernel(
    const float* __restrict__ W, const float* __restrict__ bias)
{
    const int idx = blockIdx.x * 256 + threadIdx.x;           // float4 index
    const int n4 = DMODEL * DMODEL / 4;                       // 262144
    if (idx < n4) {
        float4 v = ((const float4*)W)[idx];
        __half2 h0 = __floats2half2_rn(v.x, v.y);
        __half2 h1 = __floats2half2_rn(v.z, v.w);
        ((__half2*)g_Wh)[idx * 2]     = h0;
        ((__half2*)g_Wh)[idx * 2 + 1] = h1;
    }
    if (idx < 16 * DMODEL / 4) {
        float4 b = ((const float4*)bias)[idx & (DMODEL / 4 - 1)];
        ((float4*)g_biasrep)[idx] = b;
    }
}

// ---------------------------------------------------------------------------
// GEMM: C[16384,1024] = g_headsh(fp16) @ g_Wh(fp16) + bias, fp32 accumulate
// Block 128x128, BK=64, warp tile 64x64 (4 warps, 128 threads),
// 3-stage cp.async. WMMA m16n16k16 half. Padded rows (16B) -> LDSM
// conflict-free (row strides 9 / 17 16B-units).
// ---------------------------------------------------------------------------
#define GM 16384
#define GN 1024
#define GK 1024
#define BM 128
#define BN 128
#define BK 64
#define NKT (GK / BK)        // 16
#define STG 3
#define LDA_H 72             // padded A smem row (halfs) = 144B
#define LDB_H 136            // padded B smem row (halfs) = 272B
#define A_STG (BM * LDA_H)   // 9216 halfs
#define B_STG (BK * LDB_H)   // 8704 halfs
#define GEMM_SMEM ((STG * (A_STG + B_STG)) * 2)   // 107520 bytes

__global__ __launch_bounds__(128) void gemm_kernel(float* __restrict__ C)
{
    extern __shared__ __align__(16) __half smh[];
    const int tid = threadIdx.x;
    const int wid = tid >> 5;
    const int wm  = wid & 1;            // 0..1 (M)
    const int wn  = wid >> 1;           // 0..1 (N)
    const int bm  = blockIdx.y * BM;
    const int bn  = blockIdx.x * BN;

    const __half* Ag  = g_headsh + (size_t)bm * GK;
    const __half* Bgp = g_Wh + bn;

    const uint32_t smem_b = smem_u32(smh);

    // accumulators init from replicated bias (global load)
    wmma::fragment<wmma::accumulator, 16, 16, 16, float> cf[4][4];
#pragma unroll
    for (int i = 0; i < 4; ++i)
#pragma unroll
        for (int j = 0; j < 4; ++j)
            wmma::load_matrix_sync(cf[i][j], g_biasrep + bn + wn * 64 + j * 16,
                                   GN, wmma::mem_row_major);

    // cp.async decomposition (128 threads), 16B = 8 halfs
    const int ar = tid >> 3;            // 0..15 (+16/pass, 8 passes = 128 rows)
    const int ac = (tid & 7) * 8;       // half col 0..56
    const int br = tid >> 4;            // 0..7  (+8/pass, 8 passes = 64 rows)
    const int bc = (tid & 15) * 8;      // half col 0..120

    auto load_stage = [&](int kt, int s) {
        const int kof = kt * BK;
        uint32_t adst = smem_b + (s * A_STG) * 2;
        uint32_t bdst = smem_b + (STG * A_STG + s * B_STG) * 2;
#pragma unroll
        for (int i = 0; i < 8; ++i) {
            const int r = ar + i * 16;
            CP_ASYNC16(adst + (r * LDA_H + ac) * 2,
                       Ag + (size_t)r * GK + kof + ac);
        }
#pragma unroll
        for (int i = 0; i < 8; ++i) {
            const int r = br + i * 8;
            CP_ASYNC16(bdst + (r * LDB_H + bc) * 2,
                       Bgp + (size_t)(kof + r) * GN + bc);
        }
    };

    load_stage(0, 0); CP_COMMIT();
    load_stage(1, 1); CP_COMMIT();

    for (int c = 0; c < NKT; ++c) {
        const int s = c % 3;
        CP_WAIT1();                      // stage c complete (<=1 newer pending)
        __syncthreads();
        if (c + 2 < NKT) load_stage(c + 2, (c + 2) % 3);
        CP_COMMIT();

        const __half* As = smh + s * A_STG;
        const __half* Bs = smh + STG * A_STG + s * B_STG;
#pragma unroll
        for (int k0 = 0; k0 < BK; k0 += 16) {
            wmma::fragment<wmma::matrix_a, 16, 16, 16, half, wmma::row_major> af[4];
            wmma::fragment<wmma::matrix_b, 16, 16, 16, half, wmma::row_major> bf[4];
#pragma unroll
            for (int i = 0; i < 4; ++i)
                wmma::load_matrix_sync(af[i], As + (wm * 64 + i * 16) * LDA_H + k0, LDA_H);
#pragma unroll
            for (int j = 0; j < 4; ++j)
                wmma::load_matrix_sync(bf[j], Bs + k0 * LDB_H + wn * 64 + j * 16, LDB_H);
#pragma unroll
            for (int i = 0; i < 4; ++i)
#pragma unroll
                for (int j = 0; j < 4; ++j)
                    wmma::mma_sync(cf[i][j], af[i], bf[j], cf[i][j]);
        }
    }

#pragma unroll
    for (int i = 0; i < 4; ++i)
#pragma unroll
        for (int j = 0; j < 4; ++j)
            wmma::store_matrix_sync(
                C + (size_t)(bm + wm * 64 + i * 16) * GN + bn + wn * 64 + j * 16,
                cf[i][j], GN, wmma::mem_row_major);
}

// ---------------------------------------------------------------------------
extern "C" void kernel_launch(void* const* d_in, const int* in_sizes, int n_in,
                              void* d_out, int out_size)
{
    const float* x    = (const float*)d_in[0];
    const float* Kst  = (const float*)d_in[1];
    const float* Vst  = (const float*)d_in[2];
    const float* Wrt  = (const float*)d_in[3];
    const float* Wout = (const float*)d_in[4];
    const float* bout = (const float*)d_in[5];
    float* out = (float*)d_out;

    const int attn_smem = ATTN_SMEM_FLOATS * (int)sizeof(float);   // 201728 B
    cudaFuncSetAttribute(attn_kernel,
                         cudaFuncAttributeMaxDynamicSharedMemorySize, attn_smem);
    cudaFuncSetAttribute(gemm_kernel,
                         cudaFuncAttributeMaxDynamicSharedMemorySize, GEMM_SMEM);

    attn_kernel<<<dim3(NHEAD, NTOK / TOK_PER_BLK), ATTN_THREADS, attn_smem>>>(
        x, Kst, Vst, Wrt);
    convert_kernel<<<DMODEL * DMODEL / 4 / 256, 256>>>(Wout, bout);
    gemm_kernel<<<dim3(GN / BN, GM / BM), 128, GEMM_SMEM>>>(out);
}

// round 9
// speedup vs baseline: 3.5864x; 1.2191x over previous
#include <cuda_runtime.h>
#include <cuda_fp16.h>
#include <mma.h>
#include <math.h>
#include <stdint.h>

using namespace nvcuda;

// Problem constants
#define NTOK   16384      // B*S
#define DMODEL 1024
#define NHEAD  16
#define HD     64
#define NP     32
#define NR     8
#define NPR    256

// Scratch (allocation-free rule)
__device__ __half g_headsh[(size_t)NTOK * DMODEL];   // fp16 heads
__device__ __half g_Wh[(size_t)DMODEL * DMODEL];     // fp16 W_out [K,N]
__device__ float  g_biasrep[16 * DMODEL];            // bias replicated 16 rows

// ---------------------------------------------------------------------------
__device__ __forceinline__ uint32_t smem_u32(const void* p) {
    uint32_t a;
    asm("{ .reg .u64 t; cvta.to.shared.u64 t, %1; cvt.u32.u64 %0, t; }"
        : "=r"(a) : "l"(p));
    return a;
}
#define CP_ASYNC16(dst, src) \
    asm volatile("cp.async.cg.shared.global [%0], [%1], 16;" :: "r"(dst), "l"(src))
#define CP_COMMIT() asm volatile("cp.async.commit_group;" ::: "memory")
#define CP_WAIT1()  asm volatile("cp.async.wait_group 1;" ::: "memory")

// ---------------------------------------------------------------------------
// Warp reduction helpers
// ---------------------------------------------------------------------------
__device__ __forceinline__ float warp_max(float v) {
#pragma unroll
    for (int o = 16; o > 0; o >>= 1) v = fmaxf(v, __shfl_xor_sync(0xffffffffu, v, o));
    return v;
}
__device__ __forceinline__ float warp_sum(float v) {
#pragma unroll
    for (int o = 16; o > 0; o >>= 1) v += __shfl_xor_sync(0xffffffffu, v, o);
    return v;
}
__device__ __forceinline__ float g8_max(float v) {
#pragma unroll
    for (int o = 4; o > 0; o >>= 1) v = fmaxf(v, __shfl_xor_sync(0xffffffffu, v, o));
    return v;
}
__device__ __forceinline__ float g8_sum(float v) {
#pragma unroll
    for (int o = 4; o > 0; o >>= 1) v += __shfl_xor_sync(0xffffffffu, v, o);
    return v;
}

// ---------------------------------------------------------------------------
// Attention kernel: one block = (head, 512-token chunk), 32 warps.
// R9: K/V in SMEM as fp16 (halves score+combine crossbar traffic);
//     Phase B interleaves two tokens' top-k chains (hides SHFL latency).
// ---------------------------------------------------------------------------
#define ATTN_THREADS 1024
#define ATTN_WARPS   32
#define TOK_PER_BLK  512
#define CHUNK 128
#define KROWH 72          // padded K/V row in halfs (144B = 9 x 16B)
#define XTROW 132
// floats: Wr 2048 | Ks 9216 | Vs 9216 | xT 8448 | lg 4096 | xs 4096
#define ATTN_SMEM_FLOATS (2048 + 9216 + 9216 + 64 * XTROW + CHUNK * 32 + 4096)

__global__ __launch_bounds__(ATTN_THREADS) void attn_kernel(
    const float* __restrict__ x,
    const float* __restrict__ Kst,
    const float* __restrict__ Vst,
    const float* __restrict__ Wrt)
{
    extern __shared__ float sm[];
    float*  Wr_s = sm;                          // [64][32]
    __half* Ksh  = (__half*)(sm + 2048);        // [256][72] halfs
    __half* Vsh  = (__half*)(sm + 2048 + 9216); // [256][72] halfs
    float*  xT   = sm + 2048 + 18432;           // [64][132] swizzled
    float*  lg_s = xT + 64 * XTROW;             // [128][32]
    float*  xs   = lg_s + CHUNK * 32;           // [32][2][64]

    const int h    = blockIdx.x;
    const int tid  = threadIdx.x;
    const int wid  = tid >> 5;
    const int lane = tid & 31;
    const unsigned FULL = 0xffffffffu;

    for (int i = tid; i < HD * NP; i += ATTN_THREADS)
        Wr_s[i] = Wrt[h * HD * NP + i];
    const float* Kh = Kst + (size_t)h * NPR * HD;
    const float* Vh = Vst + (size_t)h * NPR * HD;
    for (int i = tid; i < NPR * HD / 2; i += ATTN_THREADS) {
        const int pr = i >> 5, d2 = i & 31;     // 32 half2 per row
        float2 kv = *(const float2*)(Kh + pr * HD + 2 * d2);
        ((__half2*)(Ksh + pr * KROWH))[d2] = __floats2half2_rn(kv.x, kv.y);
        float2 vv = *(const float2*)(Vh + pr * HD + 2 * d2);
        ((__half2*)(Vsh + pr * KROWH))[d2] = __floats2half2_rn(vv.x, vv.y);
    }
    __syncthreads();

    const int e8 = lane >> 3;
    const int r8 = lane & 7;

    // fill decomposition: tok_local = tid>>3 (0..127), j = tid&7 (d-group)
    const int f_tok = tid >> 3;
    const int f_j   = tid & 7;
    const int f_col = ((f_tok & ~3) ^ (f_j << 2)) | (f_tok & 3);

    const int blockbase = blockIdx.y * TOK_PER_BLK;

    for (int cc = 0; cc < TOK_PER_BLK / CHUNK; ++cc) {
        // ---- Phase F: stage x chunk into swizzled d-major xT ----
        {
            const int tk = blockbase + cc * CHUNK + f_tok;
            const float4* gx = (const float4*)(x + (size_t)tk * DMODEL + h * HD);
            float4 v0 = gx[f_j * 2];
            float4 v1 = gx[f_j * 2 + 1];
            float* dst = xT + (8 * f_j) * XTROW + f_col;
            dst[0 * XTROW] = v0.x; dst[1 * XTROW] = v0.y;
            dst[2 * XTROW] = v0.z; dst[3 * XTROW] = v0.w;
            dst[4 * XTROW] = v1.x; dst[5 * XTROW] = v1.y;
            dst[6 * XTROW] = v1.z; dst[7 * XTROW] = v1.w;
        }
        __syncthreads();

        // ---- Phase A: logits for 4 tokens per warp (lane = expert) ----
        {
            float a0 = 0.f, a1 = 0.f, a2 = 0.f, a3 = 0.f;
#pragma unroll
            for (int d = 0; d < HD; ++d) {
                const float wr = Wr_s[d * NP + lane];
                const int col4 = (4 * wid) ^ (((d >> 3)) << 2);
                const float4 xv = *(const float4*)(xT + d * XTROW + col4);
                a0 = fmaf(xv.x, wr, a0);
                a1 = fmaf(xv.y, wr, a1);
                a2 = fmaf(xv.z, wr, a2);
                a3 = fmaf(xv.w, wr, a3);
            }
            lg_s[(4 * wid + 0) * 32 + lane] = a0;
            lg_s[(4 * wid + 1) * 32 + lane] = a1;
            lg_s[(4 * wid + 2) * 32 + lane] = a2;
            lg_s[(4 * wid + 3) * 32 + lane] = a3;
        }
        __syncthreads();

        // ---- Phase B: 2 iterations x (2 tokens interleaved) per warp ----
        for (int it2 = 0; it2 < CHUNK / (ATTN_WARPS * 2); ++it2) {
            int   pa0[2], pa1[2], pa2[2], pa3[2];
            float ga0[2], ga1[2], ga2[2], ga3[2];

            // interleaved top-k / gates for both tokens (independent chains)
#pragma unroll
            for (int u = 0; u < 2; ++u) {
                const int tok_local = it2 * 64 + u * 32 + wid;
                const float lg = lg_s[tok_local * 32 + lane];

                float m0  = warp_max(lg);
                float cur = lg, mm = m0;
#pragma unroll
                for (int i = 0; i < 3; ++i) {
                    cur = (cur == mm) ? -INFINITY : cur;
                    mm  = warp_max(cur);
                }
                const bool sel = (lg >= mm);
                float ev   = sel ? __expf(lg - m0) : 0.f;
                float gate = ev / warp_sum(ev);

                unsigned b = __ballot_sync(FULL, sel);
                int q0 = __ffs(b) - 1; b &= b - 1;
                int q1 = __ffs(b) - 1; b &= b - 1;
                int q2 = __ffs(b) - 1; b &= b - 1;
                int q3 = __ffs(b) - 1;
                if (q0 < 0) q0 = 0;
                if (q1 < 0) q1 = q0;
                if (q2 < 0) q2 = q1;
                if (q3 < 0) q3 = q2;
                pa0[u] = q0; pa1[u] = q1; pa2[u] = q2; pa3[u] = q3;
                ga0[u] = __shfl_sync(FULL, gate, q0);
                ga1[u] = __shfl_sync(FULL, gate, q1);
                ga2[u] = __shfl_sync(FULL, gate, q2);
                ga3[u] = __shfl_sync(FULL, gate, q3);
            }

            // sequential scores + combine per token (bounded registers)
#pragma unroll
            for (int u = 0; u < 2; ++u) {
                const int tok_local = it2 * 64 + u * 32 + wid;
                const int tk = blockbase + cc * CHUNK + tok_local;
                float* xw = xs + wid * 128 + u * 64;

                const float* xp = x + (size_t)tk * DMODEL + h * HD;
                float2 xv = ((const float2*)xp)[lane];
                xw[2 * lane]     = xv.x;
                xw[2 * lane + 1] = xv.y;
                __syncwarp();

                const int   p_my = (e8 == 0) ? pa0[u] : (e8 == 1) ? pa1[u]
                                 : (e8 == 2) ? pa2[u] : pa3[u];
                const float g_my = (e8 == 0) ? ga0[u] : (e8 == 1) ? ga1[u]
                                 : (e8 == 2) ? ga2[u] : ga3[u];

                // scores: fp16 K rows, fp32 math
                const __half* kr = Ksh + (p_my * NR + r8) * KROWH;
                float s0 = 0.f, s1 = 0.f, s2 = 0.f, s3 = 0.f;
#pragma unroll
                for (int d = 0; d < HD; d += 8) {
                    uint4 kk = *(const uint4*)(kr + d);
                    float2 k0 = __half22float2(*(__half2*)&kk.x);
                    float2 k1 = __half22float2(*(__half2*)&kk.y);
                    float2 k2 = __half22float2(*(__half2*)&kk.z);
                    float2 k3 = __half22float2(*(__half2*)&kk.w);
                    const float4 xq0 = *(const float4*)(xw + d);
                    const float4 xq1 = *(const float4*)(xw + d + 4);
                    s0 = fmaf(xq0.x, k0.x, s0);
                    s1 = fmaf(xq0.y, k0.y, s1);
                    s2 = fmaf(xq0.z, k1.x, s2);
                    s3 = fmaf(xq0.w, k1.y, s3);
                    s0 = fmaf(xq1.x, k2.x, s0);
                    s1 = fmaf(xq1.y, k2.y, s1);
                    s2 = fmaf(xq1.z, k3.x, s2);
                    s3 = fmaf(xq1.w, k3.y, s3);
                }
                float sc = ((s0 + s1) + (s2 + s3)) * 0.125f;

                const float sm8 = g8_max(sc);
                const float ex  = __expf(sc - sm8);
                const float wv  = (ex / g8_sum(ex)) * g_my;

                // combine: fp16 V rows, lane owns dims (2lane, 2lane+1)
                float a0x = 0.f, a0y = 0.f, a1x = 0.f, a1y = 0.f;
#pragma unroll
                for (int j = 0; j < 32; j += 2) {
                    const float wj0 = __shfl_sync(FULL, wv, j);
                    const float wj1 = __shfl_sync(FULL, wv, j + 1);
                    const int pj0 = (j < 8) ? pa0[u] : (j < 16) ? pa1[u]
                                  : (j < 24) ? pa2[u] : pa3[u];
                    const int jb  = j + 1;
                    const int pj1 = (jb < 8) ? pa0[u] : (jb < 16) ? pa1[u]
                                  : (jb < 24) ? pa2[u] : pa3[u];
                    const __half2 h0 =
                        ((const __half2*)(Vsh + (pj0 * NR + (j & 7)) * KROWH))[lane];
                    const __half2 h1 =
                        ((const __half2*)(Vsh + (pj1 * NR + (jb & 7)) * KROWH))[lane];
                    const float2 v0 = __half22float2(h0);
                    const float2 v1 = __half22float2(h1);
                    a0x = fmaf(wj0, v0.x, a0x);
                    a0y = fmaf(wj0, v0.y, a0y);
                    a1x = fmaf(wj1, v1.x, a1x);
                    a1y = fmaf(wj1, v1.y, a1y);
                }

                __half2 hh = __floats2half2_rn(a0x + a1x, a0y + a1y);
                ((__half2*)(g_headsh + (size_t)tk * DMODEL + h * HD))[lane] = hh;
                __syncwarp();
            }
        }
        __syncthreads();   // lg_s/xT reuse safety for next chunk
    }
}

// ---------------------------------------------------------------------------
// Convert W_out -> fp16 and replicate bias into 16 rows
// ---------------------------------------------------------------------------
__global__ __launch_bounds__(256) void convert_kernel(
    const float* __restrict__ W, const float* __restrict__ bias)
{
    const int idx = blockIdx.x * 256 + threadIdx.x;           // float4 index
    const int n4 = DMODEL * DMODEL / 4;                       // 262144
    if (idx < n4) {
        float4 v = ((const float4*)W)[idx];
        __half2 h0 = __floats2half2_rn(v.x, v.y);
        __half2 h1 = __floats2half2_rn(v.z, v.w);
        ((__half2*)g_Wh)[idx * 2]     = h0;
        ((__half2*)g_Wh)[idx * 2 + 1] = h1;
    }
    if (idx < 16 * DMODEL / 4) {
        float4 b = ((const float4*)bias)[idx & (DMODEL / 4 - 1)];
        ((float4*)g_biasrep)[idx] = b;
    }
}

// ---------------------------------------------------------------------------
// GEMM: C[16384,1024] = g_headsh(fp16) @ g_Wh(fp16) + bias, fp32 accumulate
// (unchanged from R8 — measured ~104us)
// ---------------------------------------------------------------------------
#define GM 16384
#define GN 1024
#define GK 1024
#define BM 128
#define BN 128
#define BK 64
#define NKT (GK / BK)        // 16
#define STG 3
#define LDA_H 72             // padded A smem row (halfs) = 144B
#define LDB_H 136            // padded B smem row (halfs) = 272B
#define A_STG (BM * LDA_H)   // 9216 halfs
#define B_STG (BK * LDB_H)   // 8704 halfs
#define GEMM_SMEM ((STG * (A_STG + B_STG)) * 2)   // 107520 bytes

__global__ __launch_bounds__(128) void gemm_kernel(float* __restrict__ C)
{
    extern __shared__ __align__(16) __half smh[];
    const int tid = threadIdx.x;
    const int wid = tid >> 5;
    const int wm  = wid & 1;            // 0..1 (M)
    const int wn  = wid >> 1;           // 0..1 (N)
    const int bm  = blockIdx.y * BM;
    const int bn  = blockIdx.x * BN;

    const __half* Ag  = g_headsh + (size_t)bm * GK;
    const __half* Bgp = g_Wh + bn;

    const uint32_t smem_b = smem_u32(smh);

    wmma::fragment<wmma::accumulator, 16, 16, 16, float> cf[4][4];
#pragma unroll
    for (int i = 0; i < 4; ++i)
#pragma unroll
        for (int j = 0; j < 4; ++j)
            wmma::load_matrix_sync(cf[i][j], g_biasrep + bn + wn * 64 + j * 16,
                                   GN, wmma::mem_row_major);

    const int ar = tid >> 3;            // 0..15 (+16/pass, 8 passes = 128 rows)
    const int ac = (tid & 7) * 8;       // half col 0..56
    const int br = tid >> 4;            // 0..7  (+8/pass, 8 passes = 64 rows)
    const int bc = (tid & 15) * 8;      // half col 0..120

    auto load_stage = [&](int kt, int s) {
        const int kof = kt * BK;
        uint32_t adst = smem_b + (s * A_STG) * 2;
        uint32_t bdst = smem_b + (STG * A_STG + s * B_STG) * 2;
#pragma unroll
        for (int i = 0; i < 8; ++i) {
            const int r = ar + i * 16;
            CP_ASYNC16(adst + (r * LDA_H + ac) * 2,
                       Ag + (size_t)r * GK + kof + ac);
        }
#pragma unroll
        for (int i = 0; i < 8; ++i) {
            const int r = br + i * 8;
            CP_ASYNC16(bdst + (r * LDB_H + bc) * 2,
                       Bgp + (size_t)(kof + r) * GN + bc);
        }
    };

    load_stage(0, 0); CP_COMMIT();
    load_stage(1, 1); CP_COMMIT();

    for (int c = 0; c < NKT; ++c) {
        const int s = c % 3;
        CP_WAIT1();
        __syncthreads();
        if (c + 2 < NKT) load_stage(c + 2, (c + 2) % 3);
        CP_COMMIT();

        const __half* As = smh + s * A_STG;
        const __half* Bs = smh + STG * A_STG + s * B_STG;
#pragma unroll
        for (int k0 = 0; k0 < BK; k0 += 16) {
            wmma::fragment<wmma::matrix_a, 16, 16, 16, half, wmma::row_major> af[4];
            wmma::fragment<wmma::matrix_b, 16, 16, 16, half, wmma::row_major> bf[4];
#pragma unroll
            for (int i = 0; i < 4; ++i)
                wmma::load_matrix_sync(af[i], As + (wm * 64 + i * 16) * LDA_H + k0, LDA_H);
#pragma unroll
            for (int j = 0; j < 4; ++j)
                wmma::load_matrix_sync(bf[j], Bs + k0 * LDB_H + wn * 64 + j * 16, LDB_H);
#pragma unroll
            for (int i = 0; i < 4; ++i)
#pragma unroll
                for (int j = 0; j < 4; ++j)
                    wmma::mma_sync(cf[i][j], af[i], bf[j], cf[i][j]);
        }
    }

#pragma unroll
    for (int i = 0; i < 4; ++i)
#pragma unroll
        for (int j = 0; j < 4; ++j)
            wmma::store_matrix_sync(
                C + (size_t)(bm + wm * 64 + i * 16) * GN + bn + wn * 64 + j * 16,
                cf[i][j], GN, wmma::mem_row_major);
}

// ---------------------------------------------------------------------------
extern "C" void kernel_launch(void* const* d_in, const int* in_sizes, int n_in,
                              void* d_out, int out_size)
{
    const float* x    = (const float*)d_in[0];
    const float* Kst  = (const float*)d_in[1];
    const float* Vst  = (const float*)d_in[2];
    const float* Wrt  = (const float*)d_in[3];
    const float* Wout = (const float*)d_in[4];
    const float* bout = (const float*)d_in[5];
    float* out = (float*)d_out;

    const int attn_smem = ATTN_SMEM_FLOATS * (int)sizeof(float);   // 148480 B
    cudaFuncSetAttribute(attn_kernel,
                         cudaFuncAttributeMaxDynamicSharedMemorySize, attn_smem);
    cudaFuncSetAttribute(gemm_kernel,
                         cudaFuncAttributeMaxDynamicSharedMemorySize, GEMM_SMEM);

    attn_kernel<<<dim3(NHEAD, NTOK / TOK_PER_BLK), ATTN_THREADS, attn_smem>>>(
        x, Kst, Vst, Wrt);
    convert_kernel<<<DMODEL * DMODEL / 4 / 256, 256>>>(Wout, bout);
    gemm_kernel<<<dim3(GN / BN, GM / BM), 128, GEMM_SMEM>>>(out);
}

// round 10
// speedup vs baseline: 3.7542x; 1.0468x over previous
#include <cuda_runtime.h>
#include <cuda_fp16.h>
#include <mma.h>
#include <math.h>
#include <stdint.h>

using namespace nvcuda;

// Problem constants
#define NTOK   16384      // B*S
#define DMODEL 1024
#define NHEAD  16
#define HD     64
#define NP     32
#define NR     8
#define NPR    256

// Scratch (allocation-free rule)
__device__ __half g_headsh[(size_t)NTOK * DMODEL];   // fp16 heads
__device__ __half g_Wh[(size_t)DMODEL * DMODEL];     // fp16 W_out [K,N]
__device__ float  g_biasrep[16 * DMODEL];            // bias replicated 16 rows

// ---------------------------------------------------------------------------
__device__ __forceinline__ uint32_t smem_u32(const void* p) {
    uint32_t a;
    asm("{ .reg .u64 t; cvta.to.shared.u64 t, %1; cvt.u32.u64 %0, t; }"
        : "=r"(a) : "l"(p));
    return a;
}
#define CP_ASYNC16(dst, src) \
    asm volatile("cp.async.cg.shared.global [%0], [%1], 16;" :: "r"(dst), "l"(src))
#define CP_COMMIT() asm volatile("cp.async.commit_group;" ::: "memory")
#define CP_WAIT1()  asm volatile("cp.async.wait_group 1;" ::: "memory")

// single-instruction warp reduction (sm_80+ generic PTX)
#define REDUX_MAX_U32(d, s, mask) \
    asm volatile("redux.sync.max.u32 %0, %1, %2;" : "=r"(d) : "r"(s), "r"(mask))

// order-preserving float<->uint mapping
__device__ __forceinline__ uint32_t f2ord(float f) {
    uint32_t b = __float_as_uint(f);
    return (b & 0x80000000u) ? ~b : (b | 0x80000000u);
}
__device__ __forceinline__ float ord2f(uint32_t u) {
    return __uint_as_float((u & 0x80000000u) ? (u & 0x7fffffffu) : ~u);
}

__device__ __forceinline__ float g8_sum(float v) {
#pragma unroll
    for (int o = 4; o > 0; o >>= 1) v += __shfl_xor_sync(0xffffffffu, v, o);
    return v;
}

// ---------------------------------------------------------------------------
// Attention kernel: one block = (head, 512-token chunk), 32 warps.
// R10: top-k via redux.sync (short serial chain), local gate denominator
//      (no warp_sum), x staged token-major in SMEM (no Phase-B global reload).
// ---------------------------------------------------------------------------
#define ATTN_THREADS 1024
#define ATTN_WARPS   32
#define TOK_PER_BLK  512
#define CHUNK 128
#define KROWH 72          // padded K/V row in halfs (144B = 9 x 16B)
#define XTROW 132
#define XSROW 68          // token-major x row (272B = 17 x 16B)
// floats: Wr 2048 | Ksh 9216 | Vsh 9216 | xT 8448 | lg 4096 | xsT 8704
#define ATTN_SMEM_FLOATS (2048 + 9216 + 9216 + 64 * XTROW + CHUNK * 32 + CHUNK * XSROW)

__global__ __launch_bounds__(ATTN_THREADS) void attn_kernel(
    const float* __restrict__ x,
    const float* __restrict__ Kst,
    const float* __restrict__ Vst,
    const float* __restrict__ Wrt)
{
    extern __shared__ float sm[];
    float*  Wr_s = sm;                          // [64][32]
    __half* Ksh  = (__half*)(sm + 2048);        // [256][72] halfs
    __half* Vsh  = (__half*)(sm + 2048 + 9216); // [256][72] halfs
    float*  xT   = sm + 2048 + 18432;           // [64][132] d-major swizzled
    float*  lg_s = xT + 64 * XTROW;             // [128][32]
    float*  xsT  = lg_s + CHUNK * 32;           // [128][68] token-major

    const int h    = blockIdx.x;
    const int tid  = threadIdx.x;
    const int wid  = tid >> 5;
    const int lane = tid & 31;
    const unsigned FULL = 0xffffffffu;

    for (int i = tid; i < HD * NP; i += ATTN_THREADS)
        Wr_s[i] = Wrt[h * HD * NP + i];
    const float* Kh = Kst + (size_t)h * NPR * HD;
    const float* Vh = Vst + (size_t)h * NPR * HD;
    for (int i = tid; i < NPR * HD / 2; i += ATTN_THREADS) {
        const int pr = i >> 5, d2 = i & 31;     // 32 half2 per row
        float2 kv = *(const float2*)(Kh + pr * HD + 2 * d2);
        ((__half2*)(Ksh + pr * KROWH))[d2] = __floats2half2_rn(kv.x, kv.y);
        float2 vv = *(const float2*)(Vh + pr * HD + 2 * d2);
        ((__half2*)(Vsh + pr * KROWH))[d2] = __floats2half2_rn(vv.x, vv.y);
    }
    __syncthreads();

    const int e8 = lane >> 3;
    const int r8 = lane & 7;

    // fill decomposition: tok_local = tid>>3 (0..127), j = tid&7 (d-group)
    const int f_tok = tid >> 3;
    const int f_j   = tid & 7;
    const int f_col = ((f_tok & ~3) ^ (f_j << 2)) | (f_tok & 3);

    const int blockbase = blockIdx.y * TOK_PER_BLK;

    for (int cc = 0; cc < TOK_PER_BLK / CHUNK; ++cc) {
        // ---- Phase F: stage x chunk into d-major xT + token-major xsT ----
        {
            const int tk = blockbase + cc * CHUNK + f_tok;
            const float4* gx = (const float4*)(x + (size_t)tk * DMODEL + h * HD);
            float4 v0 = gx[f_j * 2];
            float4 v1 = gx[f_j * 2 + 1];
            float* dst = xT + (8 * f_j) * XTROW + f_col;
            dst[0 * XTROW] = v0.x; dst[1 * XTROW] = v0.y;
            dst[2 * XTROW] = v0.z; dst[3 * XTROW] = v0.w;
            dst[4 * XTROW] = v1.x; dst[5 * XTROW] = v1.y;
            dst[6 * XTROW] = v1.z; dst[7 * XTROW] = v1.w;
            float* dt = xsT + f_tok * XSROW + 8 * f_j;
            *(float4*)dt       = v0;
            *(float4*)(dt + 4) = v1;
        }
        __syncthreads();

        // ---- Phase A: logits for 4 tokens per warp (lane = expert) ----
        {
            float a0 = 0.f, a1 = 0.f, a2 = 0.f, a3 = 0.f;
#pragma unroll
            for (int d = 0; d < HD; ++d) {
                const float wr = Wr_s[d * NP + lane];
                const int col4 = (4 * wid) ^ (((d >> 3)) << 2);
                const float4 xv = *(const float4*)(xT + d * XTROW + col4);
                a0 = fmaf(xv.x, wr, a0);
                a1 = fmaf(xv.y, wr, a1);
                a2 = fmaf(xv.z, wr, a2);
                a3 = fmaf(xv.w, wr, a3);
            }
            lg_s[(4 * wid + 0) * 32 + lane] = a0;
            lg_s[(4 * wid + 1) * 32 + lane] = a1;
            lg_s[(4 * wid + 2) * 32 + lane] = a2;
            lg_s[(4 * wid + 3) * 32 + lane] = a3;
        }
        __syncthreads();

        // ---- Phase B: 2 iterations x (2 tokens interleaved top-k) ----
        for (int it2 = 0; it2 < CHUNK / (ATTN_WARPS * 2); ++it2) {
            int   pa0[2], pa1[2], pa2[2], pa3[2];
            float ga_my[2];

#pragma unroll
            for (int u = 0; u < 2; ++u) {
                const int tok_local = it2 * 64 + u * 32 + wid;
                const float lg = lg_s[tok_local * 32 + lane];

                // top-4 threshold via redux.sync in ordered-uint space
                const uint32_t uo = f2ord(lg);
                uint32_t um;
                REDUX_MAX_U32(um, uo, FULL);
                const uint32_t u0 = um;             // max (for exp shift)
                uint32_t cur = uo;
#pragma unroll
                for (int i = 0; i < 3; ++i) {
                    cur = (cur == um) ? 0u : cur;
                    REDUX_MAX_U32(um, cur, FULL);
                }
                const bool sel = (uo >= um);        // um = 4th max

                unsigned b = __ballot_sync(FULL, sel);
                int q0 = __ffs(b) - 1; b &= b - 1;
                int q1 = __ffs(b) - 1; b &= b - 1;
                int q2 = __ffs(b) - 1; b &= b - 1;
                int q3 = __ffs(b) - 1;
                if (q0 < 0) q0 = 0;
                if (q1 < 0) q1 = q0;
                if (q2 < 0) q2 = q1;
                if (q3 < 0) q3 = q2;
                pa0[u] = q0; pa1[u] = q1; pa2[u] = q2; pa3[u] = q3;

                // gates computed locally: shfl the 4 logits, local denom
                const float m0  = ord2f(u0);
                const float l0s = __shfl_sync(FULL, lg, q0);
                const float l1s = __shfl_sync(FULL, lg, q1);
                const float l2s = __shfl_sync(FULL, lg, q2);
                const float l3s = __shfl_sync(FULL, lg, q3);
                const float e0 = __expf(l0s - m0);
                const float e1 = __expf(l1s - m0);
                const float e2 = __expf(l2s - m0);
                const float e3 = __expf(l3s - m0);
                const float denom = (e0 + e1) + (e2 + e3);
                const float emy = (e8 == 0) ? e0 : (e8 == 1) ? e1
                                : (e8 == 2) ? e2 : e3;
                ga_my[u] = emy / denom;
            }

            // sequential scores + combine per token
#pragma unroll
            for (int u = 0; u < 2; ++u) {
                const int tok_local = it2 * 64 + u * 32 + wid;
                const int tk = blockbase + cc * CHUNK + tok_local;
                const float* xw = xsT + tok_local * XSROW;

                const int p_my = (e8 == 0) ? pa0[u] : (e8 == 1) ? pa1[u]
                               : (e8 == 2) ? pa2[u] : pa3[u];
                const float g_my = ga_my[u];

                // scores: fp16 K rows, fp32 math
                const __half* kr = Ksh + (p_my * NR + r8) * KROWH;
                float s0 = 0.f, s1 = 0.f, s2 = 0.f, s3 = 0.f;
#pragma unroll
                for (int d = 0; d < HD; d += 8) {
                    uint4 kk = *(const uint4*)(kr + d);
                    float2 k0 = __half22float2(*(__half2*)&kk.x);
                    float2 k1 = __half22float2(*(__half2*)&kk.y);
                    float2 k2 = __half22float2(*(__half2*)&kk.z);
                    float2 k3 = __half22float2(*(__half2*)&kk.w);
                    const float4 xq0 = *(const float4*)(xw + d);
                    const float4 xq1 = *(const float4*)(xw + d + 4);
                    s0 = fmaf(xq0.x, k0.x, s0);
                    s1 = fmaf(xq0.y, k0.y, s1);
                    s2 = fmaf(xq0.z, k1.x, s2);
                    s3 = fmaf(xq0.w, k1.y, s3);
                    s0 = fmaf(xq1.x, k2.x, s0);
                    s1 = fmaf(xq1.y, k2.y, s1);
                    s2 = fmaf(xq1.z, k3.x, s2);
                    s3 = fmaf(xq1.w, k3.y, s3);
                }
                float sc = ((s0 + s1) + (s2 + s3)) * 0.125f;

                // softmax over 8 slots: masked redux max + butterfly sum
                uint32_t um8;
                REDUX_MAX_U32(um8, f2ord(sc), 0xFFu << (8 * e8));
                const float sm8 = ord2f(um8);
                const float ex  = __expf(sc - sm8);
                const float wv  = (ex / g8_sum(ex)) * g_my;

                // combine: fp16 V rows, lane owns dims (2lane, 2lane+1)
                float a0x = 0.f, a0y = 0.f, a1x = 0.f, a1y = 0.f;
#pragma unroll
                for (int j = 0; j < 32; j += 2) {
                    const float wj0 = __shfl_sync(FULL, wv, j);
                    const float wj1 = __shfl_sync(FULL, wv, j + 1);
                    const int pj0 = (j < 8) ? pa0[u] : (j < 16) ? pa1[u]
                                  : (j < 24) ? pa2[u] : pa3[u];
                    const int jb  = j + 1;
                    const int pj1 = (jb < 8) ? pa0[u] : (jb < 16) ? pa1[u]
                                  : (jb < 24) ? pa2[u] : pa3[u];
                    const __half2 h0 =
                        ((const __half2*)(Vsh + (pj0 * NR + (j & 7)) * KROWH))[lane];
                    const __half2 h1 =
                        ((const __half2*)(Vsh + (pj1 * NR + (jb & 7)) * KROWH))[lane];
                    const float2 v0 = __half22float2(h0);
                    const float2 v1 = __half22float2(h1);
                    a0x = fmaf(wj0, v0.x, a0x);
                    a0y = fmaf(wj0, v0.y, a0y);
                    a1x = fmaf(wj1, v1.x, a1x);
                    a1y = fmaf(wj1, v1.y, a1y);
                }

                __half2 hh = __floats2half2_rn(a0x + a1x, a0y + a1y);
                ((__half2*)(g_headsh + (size_t)tk * DMODEL + h * HD))[lane] = hh;
            }
        }
        __syncthreads();   // lg_s/xT/xsT reuse safety for next chunk
    }
}

// ---------------------------------------------------------------------------
// Convert W_out -> fp16 and replicate bias into 16 rows
// ---------------------------------------------------------------------------
__global__ __launch_bounds__(256) void convert_kernel(
    const float* __restrict__ W, const float* __restrict__ bias)
{
    const int idx = blockIdx.x * 256 + threadIdx.x;           // float4 index
    const int n4 = DMODEL * DMODEL / 4;                       // 262144
    if (idx < n4) {
        float4 v = ((const float4*)W)[idx];
        __half2 h0 = __floats2half2_rn(v.x, v.y);
        __half2 h1 = __floats2half2_rn(v.z, v.w);
        ((__half2*)g_Wh)[idx * 2]     = h0;
        ((__half2*)g_Wh)[idx * 2 + 1] = h1;
    }
    if (idx < 16 * DMODEL / 4) {
        float4 b = ((const float4*)bias)[idx & (DMODEL / 4 - 1)];
        ((float4*)g_biasrep)[idx] = b;
    }
}

// ---------------------------------------------------------------------------
// GEMM: C[16384,1024] = g_headsh(fp16) @ g_Wh(fp16) + bias, fp32 accumulate
// (unchanged from R8/R9 — measured ~104us)
// ---------------------------------------------------------------------------
#define GM 16384
#define GN 1024
#define GK 1024
#define BM 128
#define BN 128
#define BK 64
#define NKT (GK / BK)        // 16
#define STG 3
#define LDA_H 72             // padded A smem row (halfs) = 144B
#define LDB_H 136            // padded B smem row (halfs) = 272B
#define A_STG (BM * LDA_H)   // 9216 halfs
#define B_STG (BK * LDB_H)   // 8704 halfs
#define GEMM_SMEM ((STG * (A_STG + B_STG)) * 2)   // 107520 bytes

__global__ __launch_bounds__(128) void gemm_kernel(float* __restrict__ C)
{
    extern __shared__ __align__(16) __half smh[];
    const int tid = threadIdx.x;
    const int wid = tid >> 5;
    const int wm  = wid & 1;            // 0..1 (M)
    const int wn  = wid >> 1;           // 0..1 (N)
    const int bm  = blockIdx.y * BM;
    const int bn  = blockIdx.x * BN;

    const __half* Ag  = g_headsh + (size_t)bm * GK;
    const __half* Bgp = g_Wh + bn;

    const uint32_t smem_b = smem_u32(smh);

    wmma::fragment<wmma::accumulator, 16, 16, 16, float> cf[4][4];
#pragma unroll
    for (int i = 0; i < 4; ++i)
#pragma unroll
        for (int j = 0; j < 4; ++j)
            wmma::load_matrix_sync(cf[i][j], g_biasrep + bn + wn * 64 + j * 16,
                                   GN, wmma::mem_row_major);

    const int ar = tid >> 3;            // 0..15 (+16/pass, 8 passes = 128 rows)
    const int ac = (tid & 7) * 8;       // half col 0..56
    const int br = tid >> 4;            // 0..7  (+8/pass, 8 passes = 64 rows)
    const int bc = (tid & 15) * 8;      // half col 0..120

    auto load_stage = [&](int kt, int s) {
        const int kof = kt * BK;
        uint32_t adst = smem_b + (s * A_STG) * 2;
        uint32_t bdst = smem_b + (STG * A_STG + s * B_STG) * 2;
#pragma unroll
        for (int i = 0; i < 8; ++i) {
            const int r = ar + i * 16;
            CP_ASYNC16(adst + (r * LDA_H + ac) * 2,
                       Ag + (size_t)r * GK + kof + ac);
        }
#pragma unroll
        for (int i = 0; i < 8; ++i) {
            const int r = br + i * 8;
            CP_ASYNC16(bdst + (r * LDB_H + bc) * 2,
                       Bgp + (size_t)(kof + r) * GN + bc);
        }
    };

    load_stage(0, 0); CP_COMMIT();
    load_stage(1, 1); CP_COMMIT();

    for (int c = 0; c < NKT; ++c) {
        const int s = c % 3;
        CP_WAIT1();
        __syncthreads();
        if (c + 2 < NKT) load_stage(c + 2, (c + 2) % 3);
        CP_COMMIT();

        const __half* As = smh + s * A_STG;
        const __half* Bs = smh + STG * A_STG + s * B_STG;
#pragma unroll
        for (int k0 = 0; k0 < BK; k0 += 16) {
            wmma::fragment<wmma::matrix_a, 16, 16, 16, half, wmma::row_major> af[4];
            wmma::fragment<wmma::matrix_b, 16, 16, 16, half, wmma::row_major> bf[4];
#pragma unroll
            for (int i = 0; i < 4; ++i)
                wmma::load_matrix_sync(af[i], As + (wm * 64 + i * 16) * LDA_H + k0, LDA_H);
#pragma unroll
            for (int j = 0; j < 4; ++j)
                wmma::load_matrix_sync(bf[j], Bs + k0 * LDB_H + wn * 64 + j * 16, LDB_H);
#pragma unroll
            for (int i = 0; i < 4; ++i)
#pragma unroll
                for (int j = 0; j < 4; ++j)
                    wmma::mma_sync(cf[i][j], af[i], bf[j], cf[i][j]);
        }
    }

#pragma unroll
    for (int i = 0; i < 4; ++i)
#pragma unroll
        for (int j = 0; j < 4; ++j)
            wmma::store_matrix_sync(
                C + (size_t)(bm + wm * 64 + i * 16) * GN + bn + wn * 64 + j * 16,
                cf[i][j], GN, wmma::mem_row_major);
}

// ---------------------------------------------------------------------------
extern "C" void kernel_launch(void* const* d_in, const int* in_sizes, int n_in,
                              void* d_out, int out_size)
{
    const float* x    = (const float*)d_in[0];
    const float* Kst  = (const float*)d_in[1];
    const float* Vst  = (const float*)d_in[2];
    const float* Wrt  = (const float*)d_in[3];
    const float* Wout = (const float*)d_in[4];
    const float* bout = (const float*)d_in[5];
    float* out = (float*)d_out;

    const int attn_smem = ATTN_SMEM_FLOATS * (int)sizeof(float);   // 166912 B
    cudaFuncSetAttribute(attn_kernel,
                         cudaFuncAttributeMaxDynamicSharedMemorySize, attn_smem);
    cudaFuncSetAttribute(gemm_kernel,
                         cudaFuncAttributeMaxDynamicSharedMemorySize, GEMM_SMEM);

    attn_kernel<<<dim3(NHEAD, NTOK / TOK_PER_BLK), ATTN_THREADS, attn_smem>>>(
        x, Kst, Vst, Wrt);
    convert_kernel<<<DMODEL * DMODEL / 4 / 256, 256>>>(Wout, bout);
    gemm_kernel<<<dim3(GN / BN, GM / BM), 128, GEMM_SMEM>>>(out);
}

// round 11
// speedup vs baseline: 4.3743x; 1.1652x over previous
#include <cuda_runtime.h>
#include <cuda_fp16.h>
#include <mma.h>
#include <math.h>
#include <stdint.h>

using namespace nvcuda;

// Problem constants
#define NTOK   16384      // B*S
#define DMODEL 1024
#define NHEAD  16
#define HD     64
#define NP     32
#define NR     8
#define NPR    256

// Scratch (allocation-free rule)
__device__ __half g_headsh[(size_t)NTOK * DMODEL];   // fp16 heads
__device__ __half g_Wh[(size_t)DMODEL * DMODEL];     // fp16 W_out [K,N]
__device__ float  g_biasrep[16 * DMODEL];            // bias replicated 16 rows

// ---------------------------------------------------------------------------
__device__ __forceinline__ uint32_t smem_u32(const void* p) {
    uint32_t a;
    asm("{ .reg .u64 t; cvta.to.shared.u64 t, %1; cvt.u32.u64 %0, t; }"
        : "=r"(a) : "l"(p));
    return a;
}
#define CP_ASYNC16(dst, src) \
    asm volatile("cp.async.cg.shared.global [%0], [%1], 16;" :: "r"(dst), "l"(src))
#define CP_COMMIT() asm volatile("cp.async.commit_group;" ::: "memory")
#define CP_WAIT1()  asm volatile("cp.async.wait_group 1;" ::: "memory")

// single-instruction warp reduction (sm_80+ generic PTX)
#define REDUX_MAX_U32(d, s, mask) \
    asm volatile("redux.sync.max.u32 %0, %1, %2;" : "=r"(d) : "r"(s), "r"(mask))

// order-preserving float<->uint mapping
__device__ __forceinline__ uint32_t f2ord(float f) {
    uint32_t b = __float_as_uint(f);
    return (b & 0x80000000u) ? ~b : (b | 0x80000000u);
}
__device__ __forceinline__ float ord2f(uint32_t u) {
    return __uint_as_float((u & 0x80000000u) ? (u & 0x7fffffffu) : ~u);
}

__device__ __forceinline__ float g8_sum(float v) {
#pragma unroll
    for (int o = 4; o > 0; o >>= 1) v += __shfl_xor_sync(0xffffffffu, v, o);
    return v;
}

// ---------------------------------------------------------------------------
// Attention kernel: one block = (head, 256-token chunk set), 32 warps.
// R11: scores fully fp16 (HFMA2 on half2 x and K), logits kept in registers
//      (warp owns the same 4 tokens in Phase A and B; no lg_s, one less
//      barrier), TOK_PER_BLK 256 for tail-wave balance.
// ---------------------------------------------------------------------------
#define ATTN_THREADS 1024
#define ATTN_WARPS   32
#define TOK_PER_BLK  256
#define CHUNK 128
#define KROWH 72          // padded K/V/x row in halfs (144B = 9 x 16B)
#define XTROW 132
// floats: Wr 2048 | Ksh 9216 | Vsh 9216 | xT 8448 | xsTh 4608
#define ATTN_SMEM_FLOATS (2048 + 9216 + 9216 + 64 * XTROW + CHUNK * KROWH / 2)

__global__ __launch_bounds__(ATTN_THREADS) void attn_kernel(
    const float* __restrict__ x,
    const float* __restrict__ Kst,
    const float* __restrict__ Vst,
    const float* __restrict__ Wrt)
{
    extern __shared__ float sm[];
    float*  Wr_s = sm;                           // [64][32]
    __half* Ksh  = (__half*)(sm + 2048);         // [256][72] halfs
    __half* Vsh  = (__half*)(sm + 11264);        // [256][72] halfs
    float*  xT   = sm + 20480;                   // [64][132] d-major swizzled
    __half* xsTh = (__half*)(sm + 20480 + 64 * XTROW);  // [128][72] halfs

    const int h    = blockIdx.x;
    const int tid  = threadIdx.x;
    const int wid  = tid >> 5;
    const int lane = tid & 31;
    const unsigned FULL = 0xffffffffu;

    for (int i = tid; i < HD * NP; i += ATTN_THREADS)
        Wr_s[i] = Wrt[h * HD * NP + i];
    const float* Kh = Kst + (size_t)h * NPR * HD;
    const float* Vh = Vst + (size_t)h * NPR * HD;
    for (int i = tid; i < NPR * HD / 2; i += ATTN_THREADS) {
        const int pr = i >> 5, d2 = i & 31;      // 32 half2 per row
        float2 kv = *(const float2*)(Kh + pr * HD + 2 * d2);
        ((__half2*)(Ksh + pr * KROWH))[d2] = __floats2half2_rn(kv.x, kv.y);
        float2 vv = *(const float2*)(Vh + pr * HD + 2 * d2);
        ((__half2*)(Vsh + pr * KROWH))[d2] = __floats2half2_rn(vv.x, vv.y);
    }
    __syncthreads();

    const int e8 = lane >> 3;
    const int r8 = lane & 7;

    // fill decomposition: tok_local = tid>>3 (0..127), j = tid&7 (d-group)
    const int f_tok = tid >> 3;
    const int f_j   = tid & 7;
    const int f_col = ((f_tok & ~3) ^ (f_j << 2)) | (f_tok & 3);

    const int blockbase = blockIdx.y * TOK_PER_BLK;

    for (int cc = 0; cc < TOK_PER_BLK / CHUNK; ++cc) {
        // ---- Phase F: stage x chunk into d-major fp32 xT + half xsTh ----
        {
            const int tk = blockbase + cc * CHUNK + f_tok;
            const float4* gx = (const float4*)(x + (size_t)tk * DMODEL + h * HD);
            float4 v0 = gx[f_j * 2];
            float4 v1 = gx[f_j * 2 + 1];
            float* dst = xT + (8 * f_j) * XTROW + f_col;
            dst[0 * XTROW] = v0.x; dst[1 * XTROW] = v0.y;
            dst[2 * XTROW] = v0.z; dst[3 * XTROW] = v0.w;
            dst[4 * XTROW] = v1.x; dst[5 * XTROW] = v1.y;
            dst[6 * XTROW] = v1.z; dst[7 * XTROW] = v1.w;
            __half2 h0 = __floats2half2_rn(v0.x, v0.y);
            __half2 h1 = __floats2half2_rn(v0.z, v0.w);
            __half2 h2 = __floats2half2_rn(v1.x, v1.y);
            __half2 h3 = __floats2half2_rn(v1.z, v1.w);
            uint4 pk;
            pk.x = *(uint32_t*)&h0; pk.y = *(uint32_t*)&h1;
            pk.z = *(uint32_t*)&h2; pk.w = *(uint32_t*)&h3;
            *(uint4*)(xsTh + f_tok * KROWH + 8 * f_j) = pk;
        }
        __syncthreads();

        // ---- Phase A: logits for own 4 tokens (4wid..4wid+3), lane=expert ----
        float la[4];
        {
            float a0 = 0.f, a1 = 0.f, a2 = 0.f, a3 = 0.f;
#pragma unroll
            for (int d = 0; d < HD; ++d) {
                const float wr = Wr_s[d * NP + lane];
                const int col4 = (4 * wid) ^ (((d >> 3)) << 2);
                const float4 xv = *(const float4*)(xT + d * XTROW + col4);
                a0 = fmaf(xv.x, wr, a0);
                a1 = fmaf(xv.y, wr, a1);
                a2 = fmaf(xv.z, wr, a2);
                a3 = fmaf(xv.w, wr, a3);
            }
            la[0] = a0; la[1] = a1; la[2] = a2; la[3] = a3;
        }
        // no barrier needed: warp consumes its own logits from registers

        // ---- Phase B: 2 passes x (2 tokens interleaved top-k) ----
#pragma unroll
        for (int pass = 0; pass < 2; ++pass) {
            int   pa0[2], pa1[2], pa2[2], pa3[2];
            float ga_my[2];

#pragma unroll
            for (int u = 0; u < 2; ++u) {
                const float lg = la[pass * 2 + u];

                // top-4 threshold via redux.sync in ordered-uint space
                const uint32_t uo = f2ord(lg);
                uint32_t um;
                REDUX_MAX_U32(um, uo, FULL);
                const uint32_t u0 = um;             // max (for exp shift)
                uint32_t cur = uo;
#pragma unroll
                for (int i = 0; i < 3; ++i) {
                    cur = (cur == um) ? 0u : cur;
                    REDUX_MAX_U32(um, cur, FULL);
                }
                const bool sel = (uo >= um);        // um = 4th max

                unsigned b = __ballot_sync(FULL, sel);
                int q0 = __ffs(b) - 1; b &= b - 1;
                int q1 = __ffs(b) - 1; b &= b - 1;
                int q2 = __ffs(b) - 1; b &= b - 1;
                int q3 = __ffs(b) - 1;
                if (q0 < 0) q0 = 0;
                if (q1 < 0) q1 = q0;
                if (q2 < 0) q2 = q1;
                if (q3 < 0) q3 = q2;
                pa0[u] = q0; pa1[u] = q1; pa2[u] = q2; pa3[u] = q3;

                // gates computed locally: shfl the 4 logits, local denom
                const float m0  = ord2f(u0);
                const float l0s = __shfl_sync(FULL, lg, q0);
                const float l1s = __shfl_sync(FULL, lg, q1);
                const float l2s = __shfl_sync(FULL, lg, q2);
                const float l3s = __shfl_sync(FULL, lg, q3);
                const float e0 = __expf(l0s - m0);
                const float e1 = __expf(l1s - m0);
                const float e2 = __expf(l2s - m0);
                const float e3 = __expf(l3s - m0);
                const float denom = (e0 + e1) + (e2 + e3);
                const float emy = (e8 == 0) ? e0 : (e8 == 1) ? e1
                                : (e8 == 2) ? e2 : e3;
                ga_my[u] = emy / denom;
            }

            // sequential scores + combine per token
#pragma unroll
            for (int u = 0; u < 2; ++u) {
                const int tok_local = 4 * wid + pass * 2 + u;
                const int tk = blockbase + cc * CHUNK + tok_local;

                const int p_my = (e8 == 0) ? pa0[u] : (e8 == 1) ? pa1[u]
                               : (e8 == 2) ? pa2[u] : pa3[u];
                const float g_my = ga_my[u];

                // scores: fp16 HFMA2 on half2 x and K
                const __half2* kr2 =
                    (const __half2*)(Ksh + (p_my * NR + r8) * KROWH);
                const __half2* xr2 =
                    (const __half2*)(xsTh + tok_local * KROWH);
                __half2 ac0 = __float2half2_rn(0.f);
                __half2 ac1 = ac0, ac2 = ac0, ac3 = ac0;
#pragma unroll
                for (int q = 0; q < 8; ++q) {
                    const uint4 kk = *(const uint4*)(kr2 + q * 4);
                    const uint4 xx = *(const uint4*)(xr2 + q * 4);
                    ac0 = __hfma2(*(const __half2*)&xx.x,
                                  *(const __half2*)&kk.x, ac0);
                    ac1 = __hfma2(*(const __half2*)&xx.y,
                                  *(const __half2*)&kk.y, ac1);
                    ac2 = __hfma2(*(const __half2*)&xx.z,
                                  *(const __half2*)&kk.z, ac2);
                    ac3 = __hfma2(*(const __half2*)&xx.w,
                                  *(const __half2*)&kk.w, ac3);
                }
                const float2 f0 = __half22float2(__hadd2(ac0, ac1));
                const float2 f1 = __half22float2(__hadd2(ac2, ac3));
                float sc = ((f0.x + f0.y) + (f1.x + f1.y)) * 0.125f;

                // softmax over 8 slots: masked redux max + butterfly sum
                uint32_t um8;
                REDUX_MAX_U32(um8, f2ord(sc), 0xFFu << (8 * e8));
                const float sm8 = ord2f(um8);
                const float ex  = __expf(sc - sm8);
                const float wv  = (ex / g8_sum(ex)) * g_my;

                // combine: fp16 V rows, fp32 accumulate, lane owns 2 dims
                float a0x = 0.f, a0y = 0.f, a1x = 0.f, a1y = 0.f;
#pragma unroll
                for (int j = 0; j < 32; j += 2) {
                    const float wj0 = __shfl_sync(FULL, wv, j);
                    const float wj1 = __shfl_sync(FULL, wv, j + 1);
                    const int pj0 = (j < 8) ? pa0[u] : (j < 16) ? pa1[u]
                                  : (j < 24) ? pa2[u] : pa3[u];
                    const int jb  = j + 1;
                    const int pj1 = (jb < 8) ? pa0[u] : (jb < 16) ? pa1[u]
                                  : (jb < 24) ? pa2[u] : pa3[u];
                    const __half2 h0 =
                        ((const __half2*)(Vsh + (pj0 * NR + (j & 7)) * KROWH))[lane];
                    const __half2 h1 =
                        ((const __half2*)(Vsh + (pj1 * NR + (jb & 7)) * KROWH))[lane];
                    const float2 v0 = __half22float2(h0);
                    const float2 v1 = __half22float2(h1);
                    a0x = fmaf(wj0, v0.x, a0x);
                    a0y = fmaf(wj0, v0.y, a0y);
                    a1x = fmaf(wj1, v1.x, a1x);
                    a1y = fmaf(wj1, v1.y, a1y);
                }

                __half2 hh = __floats2half2_rn(a0x + a1x, a0y + a1y);
                ((__half2*)(g_headsh + (size_t)tk * DMODEL + h * HD))[lane] = hh;
            }
        }
        __syncthreads();   // xT/xsTh reuse safety for next chunk
    }
}

// ---------------------------------------------------------------------------
// Convert W_out -> fp16 and replicate bias into 16 rows
// ---------------------------------------------------------------------------
__global__ __launch_bounds__(256) void convert_kernel(
    const float* __restrict__ W, const float* __restrict__ bias)
{
    const int idx = blockIdx.x * 256 + threadIdx.x;           // float4 index
    const int n4 = DMODEL * DMODEL / 4;                       // 262144
    if (idx < n4) {
        float4 v = ((const float4*)W)[idx];
        __half2 h0 = __floats2half2_rn(v.x, v.y);
        __half2 h1 = __floats2half2_rn(v.z, v.w);
        ((__half2*)g_Wh)[idx * 2]     = h0;
        ((__half2*)g_Wh)[idx * 2 + 1] = h1;
    }
    if (idx < 16 * DMODEL / 4) {
        float4 b = ((const float4*)bias)[idx & (DMODEL / 4 - 1)];
        ((float4*)g_biasrep)[idx] = b;
    }
}

// ---------------------------------------------------------------------------
// GEMM: C[16384,1024] = g_headsh(fp16) @ g_Wh(fp16) + bias, fp32 accumulate
// (unchanged from R8-R10 — measured ~104us)
// ---------------------------------------------------------------------------
#define GM 16384
#define GN 1024
#define GK 1024
#define BM 128
#define BN 128
#define BK 64
#define NKT (GK / BK)        // 16
#define STG 3
#define LDA_H 72             // padded A smem row (halfs) = 144B
#define LDB_H 136            // padded B smem row (halfs) = 272B
#define A_STG (BM * LDA_H)   // 9216 halfs
#define B_STG (BK * LDB_H)   // 8704 halfs
#define GEMM_SMEM ((STG * (A_STG + B_STG)) * 2)   // 107520 bytes

__global__ __launch_bounds__(128) void gemm_kernel(float* __restrict__ C)
{
    extern __shared__ __align__(16) __half smh[];
    const int tid = threadIdx.x;
    const int wid = tid >> 5;
    const int wm  = wid & 1;            // 0..1 (M)
    const int wn  = wid >> 1;           // 0..1 (N)
    const int bm  = blockIdx.y * BM;
    const int bn  = blockIdx.x * BN;

    const __half* Ag  = g_headsh + (size_t)bm * GK;
    const __half* Bgp = g_Wh + bn;

    const uint32_t smem_b = smem_u32(smh);

    wmma::fragment<wmma::accumulator, 16, 16, 16, float> cf[4][4];
#pragma unroll
    for (int i = 0; i < 4; ++i)
#pragma unroll
        for (int j = 0; j < 4; ++j)
            wmma::load_matrix_sync(cf[i][j], g_biasrep + bn + wn * 64 + j * 16,
                                   GN, wmma::mem_row_major);

    const int ar = tid >> 3;            // 0..15 (+16/pass, 8 passes = 128 rows)
    const int ac = (tid & 7) * 8;       // half col 0..56
    const int br = tid >> 4;            // 0..7  (+8/pass, 8 passes = 64 rows)
    const int bc = (tid & 15) * 8;      // half col 0..120

    auto load_stage = [&](int kt, int s) {
        const int kof = kt * BK;
        uint32_t adst = smem_b + (s * A_STG) * 2;
        uint32_t bdst = smem_b + (STG * A_STG + s * B_STG) * 2;
#pragma unroll
        for (int i = 0; i < 8; ++i) {
            const int r = ar + i * 16;
            CP_ASYNC16(adst + (r * LDA_H + ac) * 2,
                       Ag + (size_t)r * GK + kof + ac);
        }
#pragma unroll
        for (int i = 0; i < 8; ++i) {
            const int r = br + i * 8;
            CP_ASYNC16(bdst + (r * LDB_H + bc) * 2,
                       Bgp + (size_t)(kof + r) * GN + bc);
        }
    };

    load_stage(0, 0); CP_COMMIT();
    load_stage(1, 1); CP_COMMIT();

    for (int c = 0; c < NKT; ++c) {
        const int s = c % 3;
        CP_WAIT1();
        __syncthreads();
        if (c + 2 < NKT) load_stage(c + 2, (c + 2) % 3);
        CP_COMMIT();

        const __half* As = smh + s * A_STG;
        const __half* Bs = smh + STG * A_STG + s * B_STG;
#pragma unroll
        for (int k0 = 0; k0 < BK; k0 += 16) {
            wmma::fragment<wmma::matrix_a, 16, 16, 16, half, wmma::row_major> af[4];
            wmma::fragment<wmma::matrix_b, 16, 16, 16, half, wmma::row_major> bf[4];
#pragma unroll
            for (int i = 0; i < 4; ++i)
                wmma::load_matrix_sync(af[i], As + (wm * 64 + i * 16) * LDA_H + k0, LDA_H);
#pragma unroll
            for (int j = 0; j < 4; ++j)
                wmma::load_matrix_sync(bf[j], Bs + k0 * LDB_H + wn * 64 + j * 16, LDB_H);
#pragma unroll
            for (int i = 0; i < 4; ++i)
#pragma unroll
                for (int j = 0; j < 4; ++j)
                    wmma::mma_sync(cf[i][j], af[i], bf[j], cf[i][j]);
        }
    }

#pragma unroll
    for (int i = 0; i < 4; ++i)
#pragma unroll
        for (int j = 0; j < 4; ++j)
            wmma::store_matrix_sync(
                C + (size_t)(bm + wm * 64 + i * 16) * GN + bn + wn * 64 + j * 16,
                cf[i][j], GN, wmma::mem_row_major);
}

// ---------------------------------------------------------------------------
extern "C" void kernel_launch(void* const* d_in, const int* in_sizes, int n_in,
                              void* d_out, int out_size)
{
    const float* x    = (const float*)d_in[0];
    const float* Kst  = (const float*)d_in[1];
    const float* Vst  = (const float*)d_in[2];
    const float* Wrt  = (const float*)d_in[3];
    const float* Wout = (const float*)d_in[4];
    const float* bout = (const float*)d_in[5];
    float* out = (float*)d_out;

    const int attn_smem = ATTN_SMEM_FLOATS * (int)sizeof(float);   // 134144 B
    cudaFuncSetAttribute(attn_kernel,
                         cudaFuncAttributeMaxDynamicSharedMemorySize, attn_smem);
    cudaFuncSetAttribute(gemm_kernel,
                         cudaFuncAttributeMaxDynamicSharedMemorySize, GEMM_SMEM);

    attn_kernel<<<dim3(NHEAD, NTOK / TOK_PER_BLK), ATTN_THREADS, attn_smem>>>(
        x, Kst, Vst, Wrt);
    convert_kernel<<<DMODEL * DMODEL / 4 / 256, 256>>>(Wout, bout);
    gemm_kernel<<<dim3(GN / BN, GM / BM), 128, GEMM_SMEM>>>(out);
}

// round 12
// speedup vs baseline: 4.4392x; 1.0148x over previous
#include <cuda_runtime.h>
#include <cuda_fp16.h>
#include <mma.h>
#include <math.h>
#include <stdint.h>

using namespace nvcuda;

// Problem constants
#define NTOK   16384      // B*S
#define DMODEL 1024
#define NHEAD  16
#define HD     64
#define NP     32
#define NR     8
#define NPR    256

// Scratch (allocation-free rule)
__device__ __half g_headsh[(size_t)NTOK * DMODEL];   // fp16 heads
__device__ __half g_Wh[(size_t)DMODEL * DMODEL];     // fp16 W_out [K,N]
__device__ float  g_biasrep[16 * DMODEL];            // bias replicated 16 rows

// ---------------------------------------------------------------------------
__device__ __forceinline__ uint32_t smem_u32(const void* p) {
    uint32_t a;
    asm("{ .reg .u64 t; cvta.to.shared.u64 t, %1; cvt.u32.u64 %0, t; }"
        : "=r"(a) : "l"(p));
    return a;
}
#define CP_ASYNC16(dst, src) \
    asm volatile("cp.async.cg.shared.global [%0], [%1], 16;" :: "r"(dst), "l"(src))
#define CP_COMMIT() asm volatile("cp.async.commit_group;" ::: "memory")
#define CP_WAIT1()  asm volatile("cp.async.wait_group 1;" ::: "memory")
#define CP_WAIT0()  asm volatile("cp.async.wait_group 0;" ::: "memory")

// single-instruction warp reduction (sm_80+ generic PTX)
#define REDUX_MAX_U32(d, s, mask) \
    asm volatile("redux.sync.max.u32 %0, %1, %2;" : "=r"(d) : "r"(s), "r"(mask))

// order-preserving float<->uint mapping
__device__ __forceinline__ uint32_t f2ord(float f) {
    uint32_t b = __float_as_uint(f);
    return (b & 0x80000000u) ? ~b : (b | 0x80000000u);
}
__device__ __forceinline__ float ord2f(uint32_t u) {
    return __uint_as_float((u & 0x80000000u) ? (u & 0x7fffffffu) : ~u);
}

__device__ __forceinline__ float g8_sum(float v) {
#pragma unroll
    for (int o = 4; o > 0; o >>= 1) v += __shfl_xor_sync(0xffffffffu, v, o);
    return v;
}

// ---------------------------------------------------------------------------
// Attention kernel: one block = (head, 256-token set), 32 warps.
// R12: combine tensorized — per-token sparse weights scattered into a dense
//      fp16 Wm[128,264] (zeroed each chunk), then block-wide WMMA
//      Wm @ Vsh with fp32 accumulate replaces the per-row LDS/SHFL combine.
// ---------------------------------------------------------------------------
#define ATTN_THREADS 1024
#define ATTN_WARPS   32
#define TOK_PER_BLK  256
#define CHUNK 128
#define KROWH 72          // padded K/V/x row in halfs (144B = 9 x 16B)
#define XTROW 132
#define WMROW 264         // weight-matrix row in halfs (528B = 33 x 16B)
// floats: Wr 2048 | Ksh 9216 | Vsh 9216 | xT 8448 | xsTh 4608 | Wm 16896
#define ATTN_SMEM_FLOATS (2048 + 9216 + 9216 + 8448 + 4608 + CHUNK * WMROW / 2)

__global__ __launch_bounds__(ATTN_THREADS) void attn_kernel(
    const float* __restrict__ x,
    const float* __restrict__ Kst,
    const float* __restrict__ Vst,
    const float* __restrict__ Wrt)
{
    extern __shared__ float sm[];
    float*  Wr_s = sm;                           // [64][32]
    __half* Ksh  = (__half*)(sm + 2048);         // [256][72] halfs
    __half* Vsh  = (__half*)(sm + 11264);        // [256][72] halfs (WMMA B)
    float*  xT   = sm + 20480;                   // [64][132] d-major swizzled
    __half* xsTh = (__half*)(sm + 28928);        // [128][72] halfs
    __half* Wm   = (__half*)(sm + 33536);        // [128][264] halfs (WMMA A)

    const int h    = blockIdx.x;
    const int tid  = threadIdx.x;
    const int wid  = tid >> 5;
    const int lane = tid & 31;
    const unsigned FULL = 0xffffffffu;

    for (int i = tid; i < HD * NP; i += ATTN_THREADS)
        Wr_s[i] = Wrt[h * HD * NP + i];
    const float* Kh = Kst + (size_t)h * NPR * HD;
    const float* Vh = Vst + (size_t)h * NPR * HD;
    for (int i = tid; i < NPR * HD / 2; i += ATTN_THREADS) {
        const int pr = i >> 5, d2 = i & 31;      // 32 half2 per row
        float2 kv = *(const float2*)(Kh + pr * HD + 2 * d2);
        ((__half2*)(Ksh + pr * KROWH))[d2] = __floats2half2_rn(kv.x, kv.y);
        float2 vv = *(const float2*)(Vh + pr * HD + 2 * d2);
        ((__half2*)(Vsh + pr * KROWH))[d2] = __floats2half2_rn(vv.x, vv.y);
    }
    __syncthreads();

    const int e8 = lane >> 3;
    const int r8 = lane & 7;

    // fill decomposition: tok_local = tid>>3 (0..127), j = tid&7 (d-group)
    const int f_tok = tid >> 3;
    const int f_j   = tid & 7;
    const int f_col = ((f_tok & ~3) ^ (f_j << 2)) | (f_tok & 3);

    // MMA tile ownership: 8 m-tiles (token groups of 16) x 4 n-tiles (16 dims)
    const int mTile = wid >> 2;
    const int nTile = wid & 3;

    const int blockbase = blockIdx.y * TOK_PER_BLK;

    for (int cc = 0; cc < TOK_PER_BLK / CHUNK; ++cc) {
        const int chunkbase = blockbase + cc * CHUNK;

        // ---- Phase F: stage x chunk (fp32 xT + half xsTh); zero Wm ----
        {
            const int tk = chunkbase + f_tok;
            const float4* gx = (const float4*)(x + (size_t)tk * DMODEL + h * HD);
            float4 v0 = gx[f_j * 2];
            float4 v1 = gx[f_j * 2 + 1];
            float* dst = xT + (8 * f_j) * XTROW + f_col;
            dst[0 * XTROW] = v0.x; dst[1 * XTROW] = v0.y;
            dst[2 * XTROW] = v0.z; dst[3 * XTROW] = v0.w;
            dst[4 * XTROW] = v1.x; dst[5 * XTROW] = v1.y;
            dst[6 * XTROW] = v1.z; dst[7 * XTROW] = v1.w;
            __half2 h0 = __floats2half2_rn(v0.x, v0.y);
            __half2 h1 = __floats2half2_rn(v0.z, v0.w);
            __half2 h2 = __floats2half2_rn(v1.x, v1.y);
            __half2 h3 = __floats2half2_rn(v1.z, v1.w);
            uint4 pk;
            pk.x = *(uint32_t*)&h0; pk.y = *(uint32_t*)&h1;
            pk.z = *(uint32_t*)&h2; pk.w = *(uint32_t*)&h3;
            *(uint4*)(xsTh + f_tok * KROWH + 8 * f_j) = pk;

            // zero the weight matrix (128*264 halfs = 4224 uint4)
            uint4 z; z.x = z.y = z.z = z.w = 0u;
            uint4* wz = (uint4*)Wm;
#pragma unroll
            for (int i = tid; i < CHUNK * WMROW / 8; i += ATTN_THREADS)
                wz[i] = z;
        }
        __syncthreads();

        // ---- Phase A: logits for own 4 tokens (4wid..4wid+3), lane=expert ----
        float la[4];
        {
            float a0 = 0.f, a1 = 0.f, a2 = 0.f, a3 = 0.f;
#pragma unroll
            for (int d = 0; d < HD; ++d) {
                const float wr = Wr_s[d * NP + lane];
                const int col4 = (4 * wid) ^ (((d >> 3)) << 2);
                const float4 xv = *(const float4*)(xT + d * XTROW + col4);
                a0 = fmaf(xv.x, wr, a0);
                a1 = fmaf(xv.y, wr, a1);
                a2 = fmaf(xv.z, wr, a2);
                a3 = fmaf(xv.w, wr, a3);
            }
            la[0] = a0; la[1] = a1; la[2] = a2; la[3] = a3;
        }

        // ---- Phase B: top-k + scores + scatter weights into Wm ----
#pragma unroll
        for (int pass = 0; pass < 2; ++pass) {
            int   pa0[2], pa1[2], pa2[2], pa3[2];
            float ga_my[2];

#pragma unroll
            for (int u = 0; u < 2; ++u) {
                const float lg = la[pass * 2 + u];

                const uint32_t uo = f2ord(lg);
                uint32_t um;
                REDUX_MAX_U32(um, uo, FULL);
                const uint32_t u0 = um;             // max (for exp shift)
                uint32_t cur = uo;
#pragma unroll
                for (int i = 0; i < 3; ++i) {
                    cur = (cur == um) ? 0u : cur;
                    REDUX_MAX_U32(um, cur, FULL);
                }
                const bool sel = (uo >= um);        // um = 4th max

                unsigned b = __ballot_sync(FULL, sel);
                int q0 = __ffs(b) - 1; b &= b - 1;
                int q1 = __ffs(b) - 1; b &= b - 1;
                int q2 = __ffs(b) - 1; b &= b - 1;
                int q3 = __ffs(b) - 1;
                if (q0 < 0) q0 = 0;
                if (q1 < 0) q1 = q0;
                if (q2 < 0) q2 = q1;
                if (q3 < 0) q3 = q2;
                pa0[u] = q0; pa1[u] = q1; pa2[u] = q2; pa3[u] = q3;

                const float m0  = ord2f(u0);
                const float l0s = __shfl_sync(FULL, lg, q0);
                const float l1s = __shfl_sync(FULL, lg, q1);
                const float l2s = __shfl_sync(FULL, lg, q2);
                const float l3s = __shfl_sync(FULL, lg, q3);
                const float e0 = __expf(l0s - m0);
                const float e1 = __expf(l1s - m0);
                const float e2 = __expf(l2s - m0);
                const float e3 = __expf(l3s - m0);
                const float denom = (e0 + e1) + (e2 + e3);
                const float emy = (e8 == 0) ? e0 : (e8 == 1) ? e1
                                : (e8 == 2) ? e2 : e3;
                ga_my[u] = emy / denom;
            }

#pragma unroll
            for (int u = 0; u < 2; ++u) {
                const int tok_local = 4 * wid + pass * 2 + u;

                const int p_my = (e8 == 0) ? pa0[u] : (e8 == 1) ? pa1[u]
                               : (e8 == 2) ? pa2[u] : pa3[u];
                const float g_my = ga_my[u];

                // scores: fp16 HFMA2 on half2 x and K
                const __half2* kr2 =
                    (const __half2*)(Ksh + (p_my * NR + r8) * KROWH);
                const __half2* xr2 =
                    (const __half2*)(xsTh + tok_local * KROWH);
                __half2 ac0 = __float2half2_rn(0.f);
                __half2 ac1 = ac0, ac2 = ac0, ac3 = ac0;
#pragma unroll
                for (int q = 0; q < 8; ++q) {
                    const uint4 kk = *(const uint4*)(kr2 + q * 4);
                    const uint4 xx = *(const uint4*)(xr2 + q * 4);
                    ac0 = __hfma2(*(const __half2*)&xx.x,
                                  *(const __half2*)&kk.x, ac0);
                    ac1 = __hfma2(*(const __half2*)&xx.y,
                                  *(const __half2*)&kk.y, ac1);
                    ac2 = __hfma2(*(const __half2*)&xx.z,
                                  *(const __half2*)&kk.z, ac2);
                    ac3 = __hfma2(*(const __half2*)&xx.w,
                                  *(const __half2*)&kk.w, ac3);
                }
                const float2 f0 = __half22float2(__hadd2(ac0, ac1));
                const float2 f1 = __half22float2(__hadd2(ac2, ac3));
                float sc = ((f0.x + f0.y) + (f1.x + f1.y)) * 0.125f;

                // softmax over 8 slots (fp32)
                uint32_t um8;
                REDUX_MAX_U32(um8, f2ord(sc), 0xFFu << (8 * e8));
                const float sm8 = ord2f(um8);
                const float ex  = __expf(sc - sm8);
                const float wv  = (ex / g8_sum(ex)) * g_my;

                // scatter weight into dense Wm (fp16)
                Wm[tok_local * WMROW + p_my * NR + r8] = __float2half_rn(wv);
            }
        }
        __syncthreads();   // all scatters + zero visible

        // ---- Phase C: combine = Wm[128,256] @ Vsh[256,64] via WMMA ----
        {
            wmma::fragment<wmma::accumulator, 16, 16, 16, float> cfr;
            wmma::fill_fragment(cfr, 0.0f);
#pragma unroll
            for (int k16 = 0; k16 < 16; ++k16) {
                wmma::fragment<wmma::matrix_a, 16, 16, 16, half,
                               wmma::row_major> af;
                wmma::fragment<wmma::matrix_b, 16, 16, 16, half,
                               wmma::row_major> bf;
                wmma::load_matrix_sync(af, Wm + (mTile * 16) * WMROW + k16 * 16,
                                       WMROW);
                wmma::load_matrix_sync(bf, Vsh + (k16 * 16) * KROWH + nTile * 16,
                                       KROWH);
                wmma::mma_sync(cfr, af, bf, cfr);
            }

            // epilogue: stage fp32 [16][16] (ldm 20, per-warp slice in xT),
            // then cvt to fp16 and store to g_headsh
            float* stage = xT + wid * 320;
            wmma::store_matrix_sync(stage, cfr, 20, wmma::mem_row_major);
            __syncwarp();

            const int row = lane >> 1;
            const int cp  = (lane & 1) * 8;
            const float4 v0 = *(const float4*)(stage + row * 20 + cp);
            const float4 v1 = *(const float4*)(stage + row * 20 + cp + 4);
            __half2 h0 = __floats2half2_rn(v0.x, v0.y);
            __half2 h1 = __floats2half2_rn(v0.z, v0.w);
            __half2 h2 = __floats2half2_rn(v1.x, v1.y);
            __half2 h3 = __floats2half2_rn(v1.z, v1.w);
            uint4 pk;
            pk.x = *(uint32_t*)&h0; pk.y = *(uint32_t*)&h1;
            pk.z = *(uint32_t*)&h2; pk.w = *(uint32_t*)&h3;
            const int tk = chunkbase + mTile * 16 + row;
            *(uint4*)(g_headsh + (size_t)tk * DMODEL + h * HD +
                      nTile * 16 + cp) = pk;
        }
        __syncthreads();   // xT/xsTh/Wm reuse safety for next chunk
    }
}

// ---------------------------------------------------------------------------
// Convert W_out -> fp16 and replicate bias into 16 rows
// ---------------------------------------------------------------------------
__global__ __launch_bounds__(256) void convert_kernel(
    const float* __restrict__ W, const float* __restrict__ bias)
{
    const int idx = blockIdx.x * 256 + threadIdx.x;           // float4 index
    const int n4 = DMODEL * DMODEL / 4;                       // 262144
    if (idx < n4) {
        float4 v = ((const float4*)W)[idx];
        __half2 h0 = __floats2half2_rn(v.x, v.y);
        __half2 h1 = __floats2half2_rn(v.z, v.w);
        ((__half2*)g_Wh)[idx * 2]     = h0;
        ((__half2*)g_Wh)[idx * 2 + 1] = h1;
    }
    if (idx < 16 * DMODEL / 4) {
        float4 b = ((const float4*)bias)[idx & (DMODEL / 4 - 1)];
        ((float4*)g_biasrep)[idx] = b;
    }
}

// ---------------------------------------------------------------------------
// GEMM: C[16384,1024] = g_headsh(fp16) @ g_Wh(fp16) + bias, fp32 accumulate.
// R12: persistent CTAs (grid = 2*SMs), tile loop removes the 46%-full tail
// wave. Per-tile pipeline identical to R8-R11.
// ---------------------------------------------------------------------------
#define GM 16384
#define GN 1024
#define GK 1024
#define BM 128
#define BN 128
#define BK 64
#define NKT (GK / BK)        // 16
#define NTILES ((GM / BM) * (GN / BN))   // 1024
#define STG 3
#define LDA_H 72             // padded A smem row (halfs) = 144B
#define LDB_H 136            // padded B smem row (halfs) = 272B
#define A_STG (BM * LDA_H)   // 9216 halfs
#define B_STG (BK * LDB_H)   // 8704 halfs
#define GEMM_SMEM ((STG * (A_STG + B_STG)) * 2)   // 107520 bytes

__global__ __launch_bounds__(128) void gemm_kernel(float* __restrict__ C)
{
    extern __shared__ __align__(16) __half smh[];
    const int tid = threadIdx.x;
    const int wid = tid >> 5;
    const int wm  = wid & 1;            // 0..1 (M)
    const int wn  = wid >> 1;           // 0..1 (N)

    const uint32_t smem_b = smem_u32(smh);

    const int ar = tid >> 3;            // 0..15 (+16/pass, 8 passes = 128 rows)
    const int ac = (tid & 7) * 8;       // half col 0..56
    const int br = tid >> 4;            // 0..7  (+8/pass, 8 passes = 64 rows)
    const int bc = (tid & 15) * 8;      // half col 0..120

    for (int t = blockIdx.x; t < NTILES; t += gridDim.x) {
        const int bm = (t >> 3) * BM;
        const int bn = (t & 7) * BN;
        const __half* Ag  = g_headsh + (size_t)bm * GK;
        const __half* Bgp = g_Wh + bn;

        wmma::fragment<wmma::accumulator, 16, 16, 16, float> cf[4][4];
#pragma unroll
        for (int i = 0; i < 4; ++i)
#pragma unroll
            for (int j = 0; j < 4; ++j)
                wmma::load_matrix_sync(cf[i][j],
                                       g_biasrep + bn + wn * 64 + j * 16,
                                       GN, wmma::mem_row_major);

        auto load_stage = [&](int kt, int s) {
            const int kof = kt * BK;
            uint32_t adst = smem_b + (s * A_STG) * 2;
            uint32_t bdst = smem_b + (STG * A_STG + s * B_STG) * 2;
#pragma unroll
            for (int i = 0; i < 8; ++i) {
                const int r = ar + i * 16;
                CP_ASYNC16(adst + (r * LDA_H + ac) * 2,
                           Ag + (size_t)r * GK + kof + ac);
            }
#pragma unroll
            for (int i = 0; i < 8; ++i) {
                const int r = br + i * 8;
                CP_ASYNC16(bdst + (r * LDB_H + bc) * 2,
                           Bgp + (size_t)(kof + r) * GN + bc);
            }
        };

        load_stage(0, 0); CP_COMMIT();
        load_stage(1, 1); CP_COMMIT();

        for (int c = 0; c < NKT; ++c) {
            const int s = c % 3;
            CP_WAIT1();
            __syncthreads();
            if (c + 2 < NKT) load_stage(c + 2, (c + 2) % 3);
            CP_COMMIT();

            const __half* As = smh + s * A_STG;
            const __half* Bs = smh + STG * A_STG + s * B_STG;
#pragma unroll
            for (int k0 = 0; k0 < BK; k0 += 16) {
                wmma::fragment<wmma::matrix_a, 16, 16, 16, half,
                               wmma::row_major> af[4];
                wmma::fragment<wmma::matrix_b, 16, 16, 16, half,
                               wmma::row_major> bf[4];
#pragma unroll
                for (int i = 0; i < 4; ++i)
                    wmma::load_matrix_sync(af[i],
                        As + (wm * 64 + i * 16) * LDA_H + k0, LDA_H);
#pragma unroll
                for (int j = 0; j < 4; ++j)
                    wmma::load_matrix_sync(bf[j],
                        Bs + k0 * LDB_H + wn * 64 + j * 16, LDB_H);
#pragma unroll
                for (int i = 0; i < 4; ++i)
#pragma unroll
                    for (int j = 0; j < 4; ++j)
                        wmma::mma_sync(cf[i][j], af[i], bf[j], cf[i][j]);
            }
        }

#pragma unroll
        for (int i = 0; i < 4; ++i)
#pragma unroll
            for (int j = 0; j < 4; ++j)
                wmma::store_matrix_sync(
                    C + (size_t)(bm + wm * 64 + i * 16) * GN + bn +
                        wn * 64 + j * 16,
                    cf[i][j], GN, wmma::mem_row_major);

        CP_WAIT0();
        __syncthreads();   // smem WAR before next tile's prologue
    }
}

// ---------------------------------------------------------------------------
extern "C" void kernel_launch(void* const* d_in, const int* in_sizes, int n_in,
                              void* d_out, int out_size)
{
    const float* x    = (const float*)d_in[0];
    const float* Kst  = (const float*)d_in[1];
    const float* Vst  = (const float*)d_in[2];
    const float* Wrt  = (const float*)d_in[3];
    const float* Wout = (const float*)d_in[4];
    const float* bout = (const float*)d_in[5];
    float* out = (float*)d_out;

    const int attn_smem = ATTN_SMEM_FLOATS * (int)sizeof(float);   // 201728 B
    cudaFuncSetAttribute(attn_kernel,
                         cudaFuncAttributeMaxDynamicSharedMemorySize, attn_smem);
    cudaFuncSetAttribute(gemm_kernel,
                         cudaFuncAttributeMaxDynamicSharedMemorySize, GEMM_SMEM);

    int nsm = 148;
    cudaDeviceGetAttribute(&nsm, cudaDevAttrMultiProcessorCount, 0);

    attn_kernel<<<dim3(NHEAD, NTOK / TOK_PER_BLK), ATTN_THREADS, attn_smem>>>(
        x, Kst, Vst, Wrt);
    convert_kernel<<<DMODEL * DMODEL / 4 / 256, 256>>>(Wout, bout);
    gemm_kernel<<<2 * nsm, 128, GEMM_SMEM>>>(out);
}

// round 14
// speedup vs baseline: 4.5490x; 1.0247x over previous
#include <cuda_runtime.h>
#include <cuda_fp16.h>
#include <mma.h>
#include <math.h>
#include <stdint.h>

using namespace nvcuda;

// Problem constants
#define NTOK   16384      // B*S
#define DMODEL 1024
#define NHEAD  16
#define HD     64
#define NP     32
#define NR     8
#define NPR    256

// Scratch (allocation-free rule)
__device__ __half g_headsh[(size_t)NTOK * DMODEL];   // fp16 heads
__device__ __half g_Wh[(size_t)DMODEL * DMODEL];     // fp16 W_out [K,N]
__device__ float  g_biasrep[16 * DMODEL];            // bias replicated 16 rows

// ---------------------------------------------------------------------------
__device__ __forceinline__ uint32_t smem_u32(const void* p) {
    uint32_t a;
    asm("{ .reg .u64 t; cvta.to.shared.u64 t, %1; cvt.u32.u64 %0, t; }"
        : "=r"(a) : "l"(p));
    return a;
}
#define CP_ASYNC16(dst, src) \
    asm volatile("cp.async.cg.shared.global [%0], [%1], 16;" :: "r"(dst), "l"(src))
#define CP_COMMIT() asm volatile("cp.async.commit_group;" ::: "memory")
#define CP_WAIT1()  asm volatile("cp.async.wait_group 1;" ::: "memory")
#define CP_WAIT0()  asm volatile("cp.async.wait_group 0;" ::: "memory")

#define REDUX_MAX_U32(d, s, mask) \
    asm volatile("redux.sync.max.u32 %0, %1, %2;" : "=r"(d) : "r"(s), "r"(mask))

// order-preserving float<->uint mapping
__device__ __forceinline__ uint32_t f2ord(float f) {
    uint32_t b = __float_as_uint(f);
    return (b & 0x80000000u) ? ~b : (b | 0x80000000u);
}
__device__ __forceinline__ float ord2f(uint32_t u) {
    return __uint_as_float((u & 0x80000000u) ? (u & 0x7fffffffu) : ~u);
}

__device__ __forceinline__ float g8_sum(float v) {
#pragma unroll
    for (int o = 4; o > 0; o >>= 1) v += __shfl_xor_sync(0xffffffffu, v, o);
    return v;
}

// 5-level warp top-k helper: returns max (u0), 4th max (u4), 5th max (u5)
__device__ __forceinline__ void topk5(float lg, uint32_t& u0, uint32_t& u4,
                                      uint32_t& u5) {
    const uint32_t uo = f2ord(lg);
    uint32_t um;
    REDUX_MAX_U32(um, uo, 0xffffffffu);
    u0 = um;
    uint32_t cur = uo;
#pragma unroll
    for (int i = 0; i < 3; ++i) {
        cur = (cur == um) ? 0u : cur;
        REDUX_MAX_U32(um, cur, 0xffffffffu);
    }
    u4 = um;
    cur = (cur == um) ? 0u : cur;
    REDUX_MAX_U32(um, cur, 0xffffffffu);
    u5 = um;
}

// ---------------------------------------------------------------------------
// Attention kernel: one block = (head, 256-token set), 32 warps.
// R14: identical to R13 except LGROW 33 -> 36. R13's store_matrix_sync used
// ldm=33 floats = 132B, violating the WMMA 16-byte-multiple requirement (UB,
// rel_err 1.32). 36 floats = 144B is legal; Phase-B reads stay conflict-free
// (consecutive lanes).
// ---------------------------------------------------------------------------
#define ATTN_THREADS 1024
#define ATTN_WARPS   32
#define TOK_PER_BLK  256
#define CHUNK 128
#define KROWH 72          // padded K/V/x row in halfs (144B = 9 x 16B)
#define WHROW 40          // W_hi/W_lo row in halfs (80B = 5 x 16B)
#define LGROW 36          // logits row in floats (144B = 9 x 16B) -- WMMA-legal
#define WMROW 264         // weight-matrix row in halfs (528B = 33 x 16B)
// float offsets
#define OFF_WHI  0                       // [64][40]h  = 1280 f
#define OFF_WLO  1280                    // [64][40]h  = 1280 f
#define OFF_KSH  2560                    // [256][72]h = 9216 f
#define OFF_VSH  11776                   // [256][72]h = 9216 f
#define OFF_XHI  20992                   // [128][72]h = 4608 f
#define OFF_XLO  25600                   // [128][72]h = 4608 f
#define OFF_LG   30208                   // [128][36]f = 4608 f
#define OFF_WM   34816                   // [128][264]h = 16896 f
#define ATTN_SMEM_FLOATS 51712           // 206848 bytes

__global__ __launch_bounds__(ATTN_THREADS) void attn_kernel(
    const float* __restrict__ x,
    const float* __restrict__ Kst,
    const float* __restrict__ Vst,
    const float* __restrict__ Wrt)
{
    extern __shared__ float sm[];
    __half* Whi  = (__half*)(sm + OFF_WHI);
    __half* Wlo  = (__half*)(sm + OFF_WLO);
    __half* Ksh  = (__half*)(sm + OFF_KSH);
    __half* Vsh  = (__half*)(sm + OFF_VSH);
    __half* xhi  = (__half*)(sm + OFF_XHI);
    __half* xlo  = (__half*)(sm + OFF_XLO);
    float*  lg_s = sm + OFF_LG;
    __half* Wm   = (__half*)(sm + OFF_WM);

    const int h    = blockIdx.x;
    const int tid  = threadIdx.x;
    const int wid  = tid >> 5;
    const int lane = tid & 31;
    const unsigned FULL = 0xffffffffu;

    // stage split router weights [d][p] -> hi/lo fp16, padded rows
    for (int i = tid; i < HD * NP; i += ATTN_THREADS) {
        const int d = i >> 5, p = i & 31;
        const float w = Wrt[h * HD * NP + i];
        const __half wh = __float2half_rn(w);
        Whi[d * WHROW + p] = wh;
        Wlo[d * WHROW + p] = __float2half_rn(w - __half2float(wh));
    }
    const float* Kh = Kst + (size_t)h * NPR * HD;
    const float* Vh = Vst + (size_t)h * NPR * HD;
    for (int i = tid; i < NPR * HD / 2; i += ATTN_THREADS) {
        const int pr = i >> 5, d2 = i & 31;
        float2 kv = *(const float2*)(Kh + pr * HD + 2 * d2);
        ((__half2*)(Ksh + pr * KROWH))[d2] = __floats2half2_rn(kv.x, kv.y);
        float2 vv = *(const float2*)(Vh + pr * HD + 2 * d2);
        ((__half2*)(Vsh + pr * KROWH))[d2] = __floats2half2_rn(vv.x, vv.y);
    }
    __syncthreads();

    const int e8 = lane >> 3;
    const int r8 = lane & 7;

    // fill decomposition: tok_local = tid>>3 (0..127), j = tid&7 (d-group)
    const int f_tok = tid >> 3;
    const int f_j   = tid & 7;

    // combine MMA tile ownership: 8 m-tiles x 4 n-tiles
    const int mTile = wid >> 2;
    const int nTile = wid & 3;

    const int blockbase = blockIdx.y * TOK_PER_BLK;

    for (int cc = 0; cc < TOK_PER_BLK / CHUNK; ++cc) {
        const int chunkbase = blockbase + cc * CHUNK;

        // ---- Phase F: stage x chunk as hi/lo fp16 pairs ----
        {
            const int tk = chunkbase + f_tok;
            const float4* gx = (const float4*)(x + (size_t)tk * DMODEL + h * HD);
            float4 v0 = gx[f_j * 2];
            float4 v1 = gx[f_j * 2 + 1];
            __half2 h0 = __floats2half2_rn(v0.x, v0.y);
            __half2 h1 = __floats2half2_rn(v0.z, v0.w);
            __half2 h2 = __floats2half2_rn(v1.x, v1.y);
            __half2 h3 = __floats2half2_rn(v1.z, v1.w);
            uint4 pk;
            pk.x = *(uint32_t*)&h0; pk.y = *(uint32_t*)&h1;
            pk.z = *(uint32_t*)&h2; pk.w = *(uint32_t*)&h3;
            *(uint4*)(xhi + f_tok * KROWH + 8 * f_j) = pk;

            float2 b0 = __half22float2(h0), b1 = __half22float2(h1);
            float2 b2 = __half22float2(h2), b3 = __half22float2(h3);
            __half2 l0 = __floats2half2_rn(v0.x - b0.x, v0.y - b0.y);
            __half2 l1 = __floats2half2_rn(v0.z - b1.x, v0.w - b1.y);
            __half2 l2 = __floats2half2_rn(v1.x - b2.x, v1.y - b2.y);
            __half2 l3 = __floats2half2_rn(v1.z - b3.x, v1.w - b3.y);
            uint4 pl;
            pl.x = *(uint32_t*)&l0; pl.y = *(uint32_t*)&l1;
            pl.z = *(uint32_t*)&l2; pl.w = *(uint32_t*)&l3;
            *(uint4*)(xlo + f_tok * KROWH + 8 * f_j) = pl;
        }
        __syncthreads();

        // ---- Phase A: split-fp16 logits MMA (warps 0-15) || zero Wm ----
        if (wid < 16) {
            const int mT = wid >> 1;            // 0..7 token tile
            const int nT = wid & 1;             // 0..1 expert tile
            wmma::fragment<wmma::accumulator, 16, 16, 16, float> acc;
            wmma::fill_fragment(acc, 0.0f);
#pragma unroll
            for (int pass = 0; pass < 3; ++pass) {
                const __half* Asrc = (pass == 1) ? xlo : xhi;
                const __half* Bsrc = (pass == 2) ? Wlo : Whi;
#pragma unroll
                for (int k16 = 0; k16 < 4; ++k16) {
                    wmma::fragment<wmma::matrix_a, 16, 16, 16, half,
                                   wmma::row_major> af;
                    wmma::fragment<wmma::matrix_b, 16, 16, 16, half,
                                   wmma::row_major> bf;
                    wmma::load_matrix_sync(af,
                        Asrc + (mT * 16) * KROWH + k16 * 16, KROWH);
                    wmma::load_matrix_sync(bf,
                        Bsrc + (k16 * 16) * WHROW + nT * 16, WHROW);
                    wmma::mma_sync(acc, af, bf, acc);
                }
            }
            wmma::store_matrix_sync(lg_s + (mT * 16) * LGROW + nT * 16, acc,
                                    LGROW, wmma::mem_row_major);
        } else {
            // zero Wm: 128*264 halfs = 4224 uint4, 512 threads
            uint4 z; z.x = z.y = z.z = z.w = 0u;
            uint4* wz = (uint4*)Wm;
            const int t2 = tid - 512;
            for (int i = t2; i < CHUNK * WMROW / 8; i += 512)
                wz[i] = z;
        }
        __syncthreads();

        // ---- Phase B: top-k (+exact fallback) + scores + scatter ----
#pragma unroll
        for (int pass = 0; pass < 2; ++pass) {
            int   pa0[2], pa1[2], pa2[2], pa3[2];
            float ga_my[2];

#pragma unroll
            for (int u = 0; u < 2; ++u) {
                const int tok_local = 4 * wid + pass * 2 + u;
                float lg = lg_s[tok_local * LGROW + lane];

                uint32_t u0, u4, u5;
                topk5(lg, u0, u4, u5);

                // selection safety: if 4th/5th gap is tiny, recompute exact
                if (ord2f(u4) - ord2f(u5) < 1e-4f) {
                    const __half* xh = xhi + tok_local * KROWH;
                    const __half* xl = xlo + tok_local * KROWH;
                    float acc = 0.f;
#pragma unroll
                    for (int d = 0; d < HD; ++d) {
                        const float xv = __half2float(xh[d]) +
                                         __half2float(xl[d]);
                        const float wv = __half2float(Whi[d * WHROW + lane]) +
                                         __half2float(Wlo[d * WHROW + lane]);
                        acc = fmaf(xv, wv, acc);
                    }
                    lg = acc;
                    topk5(lg, u0, u4, u5);
                }

                const bool sel = (f2ord(lg) >= u4);
                unsigned b = __ballot_sync(FULL, sel);
                int q0 = __ffs(b) - 1; b &= b - 1;
                int q1 = __ffs(b) - 1; b &= b - 1;
                int q2 = __ffs(b) - 1; b &= b - 1;
                int q3 = __ffs(b) - 1;
                if (q0 < 0) q0 = 0;
                if (q1 < 0) q1 = q0;
                if (q2 < 0) q2 = q1;
                if (q3 < 0) q3 = q2;
                pa0[u] = q0; pa1[u] = q1; pa2[u] = q2; pa3[u] = q3;

                const float m0  = ord2f(u0);
                const float l0s = __shfl_sync(FULL, lg, q0);
                const float l1s = __shfl_sync(FULL, lg, q1);
                const float l2s = __shfl_sync(FULL, lg, q2);
                const float l3s = __shfl_sync(FULL, lg, q3);
                const float e0 = __expf(l0s - m0);
                const float e1 = __expf(l1s - m0);
                const float e2 = __expf(l2s - m0);
                const float e3 = __expf(l3s - m0);
                const float denom = (e0 + e1) + (e2 + e3);
                const float emy = (e8 == 0) ? e0 : (e8 == 1) ? e1
                                : (e8 == 2) ? e2 : e3;
                ga_my[u] = emy / denom;
            }

#pragma unroll
            for (int u = 0; u < 2; ++u) {
                const int tok_local = 4 * wid + pass * 2 + u;

                const int p_my = (e8 == 0) ? pa0[u] : (e8 == 1) ? pa1[u]
                               : (e8 == 2) ? pa2[u] : pa3[u];
                const float g_my = ga_my[u];

                // scores: fp16 HFMA2 on half2 x_hi and K
                const __half2* kr2 =
                    (const __half2*)(Ksh + (p_my * NR + r8) * KROWH);
                const __half2* xr2 =
                    (const __half2*)(xhi + tok_local * KROWH);
                __half2 ac0 = __float2half2_rn(0.f);
                __half2 ac1 = ac0, ac2 = ac0, ac3 = ac0;
#pragma unroll
                for (int q = 0; q < 8; ++q) {
                    const uint4 kk = *(const uint4*)(kr2 + q * 4);
                    const uint4 xx = *(const uint4*)(xr2 + q * 4);
                    ac0 = __hfma2(*(const __half2*)&xx.x,
                                  *(const __half2*)&kk.x, ac0);
                    ac1 = __hfma2(*(const __half2*)&xx.y,
                                  *(const __half2*)&kk.y, ac1);
                    ac2 = __hfma2(*(const __half2*)&xx.z,
                                  *(const __half2*)&kk.z, ac2);
                    ac3 = __hfma2(*(const __half2*)&xx.w,
                                  *(const __half2*)&kk.w, ac3);
                }
                const float2 f0 = __half22float2(__hadd2(ac0, ac1));
                const float2 f1 = __half22float2(__hadd2(ac2, ac3));
                float sc = ((f0.x + f0.y) + (f1.x + f1.y)) * 0.125f;

                uint32_t um8;
                REDUX_MAX_U32(um8, f2ord(sc), 0xFFu << (8 * e8));
                const float sm8 = ord2f(um8);
                const float ex  = __expf(sc - sm8);
                const float wv  = (ex / g8_sum(ex)) * g_my;

                Wm[tok_local * WMROW + p_my * NR + r8] = __float2half_rn(wv);
            }
        }
        __syncthreads();   // scatters + zero visible

        // ---- Phase C: combine = Wm[128,256] @ Vsh[256,64] via WMMA ----
        wmma::fragment<wmma::accumulator, 16, 16, 16, float> cfr;
        wmma::fill_fragment(cfr, 0.0f);
#pragma unroll
        for (int k16 = 0; k16 < 16; ++k16) {
            wmma::fragment<wmma::matrix_a, 16, 16, 16, half,
                           wmma::row_major> af;
            wmma::fragment<wmma::matrix_b, 16, 16, 16, half,
                           wmma::row_major> bf;
            wmma::load_matrix_sync(af, Wm + (mTile * 16) * WMROW + k16 * 16,
                                   WMROW);
            wmma::load_matrix_sync(bf, Vsh + (k16 * 16) * KROWH + nTile * 16,
                                   KROWH);
            wmma::mma_sync(cfr, af, bf, cfr);
        }
        __syncthreads();   // all Wm reads done before staging overwrites it

        {
            float* stage = (float*)Wm + wid * 320;
            wmma::store_matrix_sync(stage, cfr, 20, wmma::mem_row_major);
            __syncwarp();

            const int row = lane >> 1;
            const int cp  = (lane & 1) * 8;
            const float4 v0 = *(const float4*)(stage + row * 20 + cp);
            const float4 v1 = *(const float4*)(stage + row * 20 + cp + 4);
            __half2 h0 = __floats2half2_rn(v0.x, v0.y);
            __half2 h1 = __floats2half2_rn(v0.z, v0.w);
            __half2 h2 = __floats2half2_rn(v1.x, v1.y);
            __half2 h3 = __floats2half2_rn(v1.z, v1.w);
            uint4 pk;
            pk.x = *(uint32_t*)&h0; pk.y = *(uint32_t*)&h1;
            pk.z = *(uint32_t*)&h2; pk.w = *(uint32_t*)&h3;
            const int tk = chunkbase + mTile * 16 + row;
            *(uint4*)(g_headsh + (size_t)tk * DMODEL + h * HD +
                      nTile * 16 + cp) = pk;
        }
        __syncthreads();   // buffers reused next chunk
    }
}

// ---------------------------------------------------------------------------
// Convert W_out -> fp16 and replicate bias into 16 rows
// ---------------------------------------------------------------------------
__global__ __launch_bounds__(256) void convert_kernel(
    const float* __restrict__ W, const float* __restrict__ bias)
{
    const int idx = blockIdx.x * 256 + threadIdx.x;           // float4 index
    const int n4 = DMODEL * DMODEL / 4;                       // 262144
    if (idx < n4) {
        float4 v = ((const float4*)W)[idx];
        __half2 h0 = __floats2half2_rn(v.x, v.y);
        __half2 h1 = __floats2half2_rn(v.z, v.w);
        ((__half2*)g_Wh)[idx * 2]     = h0;
        ((__half2*)g_Wh)[idx * 2 + 1] = h1;
    }
    if (idx < 16 * DMODEL / 4) {
        float4 b = ((const float4*)bias)[idx & (DMODEL / 4 - 1)];
        ((float4*)g_biasrep)[idx] = b;
    }
}

// ---------------------------------------------------------------------------
// GEMM: persistent CTAs, fp16 WMMA, fp32 accumulate (unchanged from R12)
// ---------------------------------------------------------------------------
#define GM 16384
#define GN 1024
#define GK 1024
#define BM 128
#define BN 128
#define BK 64
#define NKT (GK / BK)        // 16
#define NTILES ((GM / BM) * (GN / BN))   // 1024
#define STG 3
#define LDA_H 72
#define LDB_H 136
#define A_STG (BM * LDA_H)
#define B_STG (BK * LDB_H)
#define GEMM_SMEM ((STG * (A_STG + B_STG)) * 2)   // 107520 bytes

__global__ __launch_bounds__(128) void gemm_kernel(float* __restrict__ C)
{
    extern __shared__ __align__(16) __half smh[];
    const int tid = threadIdx.x;
    const int wid = tid >> 5;
    const int wm  = wid & 1;
    const int wn  = wid >> 1;

    const uint32_t smem_b = smem_u32(smh);

    const int ar = tid >> 3;
    const int ac = (tid & 7) * 8;
    const int br = tid >> 4;
    const int bc = (tid & 15) * 8;

    for (int t = blockIdx.x; t < NTILES; t += gridDim.x) {
        const int bm = (t >> 3) * BM;
        const int bn = (t & 7) * BN;
        const __half* Ag  = g_headsh + (size_t)bm * GK;
        const __half* Bgp = g_Wh + bn;

        wmma::fragment<wmma::accumulator, 16, 16, 16, float> cf[4][4];
#pragma unroll
        for (int i = 0; i < 4; ++i)
#pragma unroll
            for (int j = 0; j < 4; ++j)
                wmma::load_matrix_sync(cf[i][j],
                                       g_biasrep + bn + wn * 64 + j * 16,
                                       GN, wmma::mem_row_major);

        auto load_stage = [&](int kt, int s) {
            const int kof = kt * BK;
            uint32_t adst = smem_b + (s * A_STG) * 2;
            uint32_t bdst = smem_b + (STG * A_STG + s * B_STG) * 2;
#pragma unroll
            for (int i = 0; i < 8; ++i) {
                const int r = ar + i * 16;
                CP_ASYNC16(adst + (r * LDA_H + ac) * 2,
                           Ag + (size_t)r * GK + kof + ac);
            }
#pragma unroll
            for (int i = 0; i < 8; ++i) {
                const int r = br + i * 8;
                CP_ASYNC16(bdst + (r * LDB_H + bc) * 2,
                           Bgp + (size_t)(kof + r) * GN + bc);
            }
        };

        load_stage(0, 0); CP_COMMIT();
        load_stage(1, 1); CP_COMMIT();

        for (int c = 0; c < NKT; ++c) {
            const int s = c % 3;
            CP_WAIT1();
            __syncthreads();
            if (c + 2 < NKT) load_stage(c + 2, (c + 2) % 3);
            CP_COMMIT();

            const __half* As = smh + s * A_STG;
            const __half* Bs = smh + STG * A_STG + s * B_STG;
#pragma unroll
            for (int k0 = 0; k0 < BK; k0 += 16) {
                wmma::fragment<wmma::matrix_a, 16, 16, 16, half,
                               wmma::row_major> af[4];
                wmma::fragment<wmma::matrix_b, 16, 16, 16, half,
                               wmma::row_major> bf[4];
#pragma unroll
                for (int i = 0; i < 4; ++i)
                    wmma::load_matrix_sync(af[i],
                        As + (wm * 64 + i * 16) * LDA_H + k0, LDA_H);
#pragma unroll
                for (int j = 0; j < 4; ++j)
                    wmma::load_matrix_sync(bf[j],
                        Bs + k0 * LDB_H + wn * 64 + j * 16, LDB_H);
#pragma unroll
                for (int i = 0; i < 4; ++i)
#pragma unroll
                    for (int j = 0; j < 4; ++j)
                        wmma::mma_sync(cf[i][j], af[i], bf[j], cf[i][j]);
            }
        }

#pragma unroll
        for (int i = 0; i < 4; ++i)
#pragma unroll
            for (int j = 0; j < 4; ++j)
                wmma::store_matrix_sync(
                    C + (size_t)(bm + wm * 64 + i * 16) * GN + bn +
                        wn * 64 + j * 16,
                    cf[i][j], GN, wmma::mem_row_major);

        CP_WAIT0();
        __syncthreads();
    }
}

// ---------------------------------------------------------------------------
extern "C" void kernel_launch(void* const* d_in, const int* in_sizes, int n_in,
                              void* d_out, int out_size)
{
    const float* x    = (const float*)d_in[0];
    const float* Kst  = (const float*)d_in[1];
    const float* Vst  = (const float*)d_in[2];
    const float* Wrt  = (const float*)d_in[3];
    const float* Wout = (const float*)d_in[4];
    const float* bout = (const float*)d_in[5];
    float* out = (float*)d_out;

    const int attn_smem = ATTN_SMEM_FLOATS * (int)sizeof(float);   // 206848 B
    cudaFuncSetAttribute(attn_kernel,
                         cudaFuncAttributeMaxDynamicSharedMemorySize, attn_smem);
    cudaFuncSetAttribute(gemm_kernel,
                         cudaFuncAttributeMaxDynamicSharedMemorySize, GEMM_SMEM);

    int nsm = 148;
    cudaDeviceGetAttribute(&nsm, cudaDevAttrMultiProcessorCount, 0);

    attn_kernel<<<dim3(NHEAD, NTOK / TOK_PER_BLK), ATTN_THREADS, attn_smem>>>(
        x, Kst, Vst, Wrt);
    convert_kernel<<<DMODEL * DMODEL / 4 / 256, 256>>>(Wout, bout);
    gemm_kernel<<<2 * nsm, 128, GEMM_SMEM>>>(out);
}